// round 4
// baseline (speedup 1.0000x reference)
#include <cuda_runtime.h>
#include <cuda_bf16.h>
#include <math.h>

// Problem constants
#define Bq 2
#define Tq 2048
#define Cq 1024
#define Hq 16
#define Dq 64
#define NCHUNK 16
#define LCHUNK 128
#define BHq (Bq * Hq)       // 32
#define Mrows (Bq * Tq)     // 4096
#define EPSq 1e-6f

// ---------------- scratch (device globals: no allocs allowed) ----------------
__device__ float g_q[(size_t)BHq * Tq * Dq];
__device__ float g_k[(size_t)BHq * Tq * Dq];
__device__ float g_v[(size_t)BHq * Tq * Dq];
__device__ float g_Sc[(size_t)BHq * NCHUNK * Dq * Dq];
__device__ float g_Sp[(size_t)BHq * NCHUNK * Dq * Dq];
__device__ float g_zc[(size_t)BHq * NCHUNK * Dq];
__device__ float g_zp[(size_t)BHq * NCHUNK * Dq];

__device__ __align__(16) __nv_bfloat16 g_xh[(size_t)Mrows * Cq];
__device__ __align__(16) __nv_bfloat16 g_xl[(size_t)Mrows * Cq];
__device__ __align__(16) __nv_bfloat16 g_wah[(size_t)Cq * 3 * Cq];
__device__ __align__(16) __nv_bfloat16 g_wal[(size_t)Cq * 3 * Cq];
__device__ __align__(16) __nv_bfloat16 g_wph[(size_t)Cq * Cq];
__device__ __align__(16) __nv_bfloat16 g_wpl[(size_t)Cq * Cq];
__device__ __align__(16) __nv_bfloat16 g_yh[(size_t)Mrows * Cq];
__device__ __align__(16) __nv_bfloat16 g_yl[(size_t)Mrows * Cq];

// ---------------- fp32 -> bf16 hi/lo split -----------------------------------
__global__ __launch_bounds__(256)
void split_kernel(const float* __restrict__ in, __nv_bfloat16* __restrict__ hi,
                  __nv_bfloat16* __restrict__ lo, int n4)
{
    const int i = blockIdx.x * 256 + threadIdx.x;
    if (i >= n4) return;
    float4 v = ((const float4*)in)[i];
    __nv_bfloat16 h0 = __float2bfloat16(v.x);
    __nv_bfloat16 h1 = __float2bfloat16(v.y);
    __nv_bfloat16 h2 = __float2bfloat16(v.z);
    __nv_bfloat16 h3 = __float2bfloat16(v.w);
    __nv_bfloat16 l0 = __float2bfloat16(v.x - __bfloat162float(h0));
    __nv_bfloat16 l1 = __float2bfloat16(v.y - __bfloat162float(h1));
    __nv_bfloat16 l2 = __float2bfloat16(v.z - __bfloat162float(h2));
    __nv_bfloat16 l3 = __float2bfloat16(v.w - __bfloat162float(h3));
    uint2 uh, ul;
    uh.x = ((unsigned)__bfloat16_as_ushort(h1) << 16) | __bfloat16_as_ushort(h0);
    uh.y = ((unsigned)__bfloat16_as_ushort(h3) << 16) | __bfloat16_as_ushort(h2);
    ul.x = ((unsigned)__bfloat16_as_ushort(l1) << 16) | __bfloat16_as_ushort(l0);
    ul.y = ((unsigned)__bfloat16_as_ushort(l3) << 16) | __bfloat16_as_ushort(l2);
    ((uint2*)hi)[i] = uh;
    ((uint2*)lo)[i] = ul;
}

// ---------------- MMA helpers ------------------------------------------------
__device__ __forceinline__ void ldsm_x4(uint4& r, unsigned addr) {
    asm volatile("ldmatrix.sync.aligned.m8n8.x4.shared.b16 {%0,%1,%2,%3}, [%4];"
                 : "=r"(r.x), "=r"(r.y), "=r"(r.z), "=r"(r.w) : "r"(addr));
}
__device__ __forceinline__ void ldsm_x4t(uint4& r, unsigned addr) {
    asm volatile("ldmatrix.sync.aligned.m8n8.x4.trans.shared.b16 {%0,%1,%2,%3}, [%4];"
                 : "=r"(r.x), "=r"(r.y), "=r"(r.z), "=r"(r.w) : "r"(addr));
}
__device__ __forceinline__ void mma_bf16(float c[4], const uint4& a, unsigned b0, unsigned b1) {
    asm volatile("mma.sync.aligned.m16n8k16.row.col.f32.bf16.bf16.f32 "
                 "{%0,%1,%2,%3},{%4,%5,%6,%7},{%8,%9},{%0,%1,%2,%3};"
                 : "+f"(c[0]), "+f"(c[1]), "+f"(c[2]), "+f"(c[3])
                 : "r"(a.x), "r"(a.y), "r"(a.z), "r"(a.w), "r"(b0), "r"(b1));
}
__device__ __forceinline__ void cp16(unsigned s, const void* g) {
    asm volatile("cp.async.cg.shared.global [%0], [%1], 16;\n" :: "r"(s), "l"(g));
}

// ---------------- bf16-split tensor-core GEMM --------------------------------
// 3-stage cp.async ring, one barrier per k-iter.
#define STAGE_BYTES 32768    // Ah 8K | Al 8K | Bh 8K | Bl 8K
#define GEMM_SMEM   (3 * STAGE_BYTES)

template <int MODE>
__global__ __launch_bounds__(256)
void mma_gemm(const __nv_bfloat16* __restrict__ Ah, const __nv_bfloat16* __restrict__ Al,
              const __nv_bfloat16* __restrict__ Bh, const __nv_bfloat16* __restrict__ Bl,
              float* __restrict__ Cout, int N)
{
    constexpr int K = 1024;
    constexpr int NITER = K / 32;
    extern __shared__ char smem[];
    const unsigned sbase = (unsigned)__cvta_generic_to_shared(smem);

    const int tid = threadIdx.x;
    const int lane = tid & 31, wid = tid >> 5;
    const int warp_m = wid >> 2, warp_n = wid & 3;
    const int bm = blockIdx.y * 128, bn = blockIdx.x * 128;

    int sA[2], sB[2], gAr[2], gAc[2], gBr[2], gBc[2];
#pragma unroll
    for (int j = 0; j < 2; j++) {
        const int f = tid + j * 256;
        const int ar = f >> 2, ac = f & 3;
        sA[j] = (ar * 4 + (ac ^ ((ar >> 1) & 3))) * 16;
        gAr[j] = ar; gAc[j] = ac * 8;
        const int br = f >> 4, bg = f & 15;
        sB[j] = (br * 16 + ((bg & 8) | ((bg & 7) ^ (br & 7)))) * 16;
        gBr[j] = br; gBc[j] = bg * 8;
    }

    const int arow_l = warp_m * 64 + (lane & 15);
    const int aghalf = (lane >> 4) & 1;
    int aOff[4][2];
#pragma unroll
    for (int mi = 0; mi < 4; mi++) {
        const int row = arow_l + mi * 16;
        const int rsw = (row >> 1) & 3;
#pragma unroll
        for (int kx = 0; kx < 2; kx++) {
            const int c = kx * 2 + aghalf;
            aOff[mi][kx] = (row * 4 + (c ^ rsw)) * 16;
        }
    }
    const int bk_l = (lane & 7) + ((lane >> 3) & 1) * 8;
    const int gadd = lane >> 4;
    const int klow = bk_l & 7;
    int bOff[2][2];
#pragma unroll
    for (int kx = 0; kx < 2; kx++) {
        const int k = kx * 16 + bk_l;
#pragma unroll
        for (int np = 0; np < 2; np++) {
            const int g = warp_n * 4 + np * 2 + gadd;
            bOff[kx][np] = (k * 16 + ((g & 8) | ((g & 7) ^ klow))) * 16;
        }
    }

    float acc[4][4][4];
#pragma unroll
    for (int mi = 0; mi < 4; mi++)
#pragma unroll
        for (int ni = 0; ni < 4; ni++)
#pragma unroll
            for (int r = 0; r < 4; r++) acc[mi][ni][r] = 0.f;

    auto issue = [&](int stage, int k0) {
        const unsigned st = sbase + stage * STAGE_BYTES;
#pragma unroll
        for (int j = 0; j < 2; j++) {
            const size_t aoff = (size_t)(bm + gAr[j]) * K + k0 + gAc[j];
            const size_t boff = (size_t)(k0 + gBr[j]) * N + bn + gBc[j];
            cp16(st + sA[j],         Ah + aoff);
            cp16(st + 8192 + sA[j],  Al + aoff);
            cp16(st + 16384 + sB[j], Bh + boff);
            cp16(st + 24576 + sB[j], Bl + boff);
        }
        asm volatile("cp.async.commit_group;");
    };

    issue(0, 0);
    issue(1, 32);

    int buf = 0, nbuf = 2;
    for (int it = 0; it < NITER; it++) {
        asm volatile("cp.async.wait_group 1;");
        __syncthreads();
        if (it + 2 < NITER) issue(nbuf, (it + 2) * 32);
        else asm volatile("cp.async.commit_group;");
        const unsigned st = sbase + buf * STAGE_BYTES;
#pragma unroll
        for (int kx = 0; kx < 2; kx++) {
            uint4 Afh[4], Afl[4], Bfh[2], Bfl[2];
#pragma unroll
            for (int mi = 0; mi < 4; mi++) {
                ldsm_x4(Afh[mi], st + aOff[mi][kx]);
                ldsm_x4(Afl[mi], st + 8192 + aOff[mi][kx]);
            }
#pragma unroll
            for (int np = 0; np < 2; np++) {
                ldsm_x4t(Bfh[np], st + 16384 + bOff[kx][np]);
                ldsm_x4t(Bfl[np], st + 24576 + bOff[kx][np]);
            }
#pragma unroll
            for (int mi = 0; mi < 4; mi++)
#pragma unroll
                for (int ni = 0; ni < 4; ni++) {
                    const int np = ni >> 1;
                    const unsigned bh0 = (ni & 1) ? Bfh[np].z : Bfh[np].x;
                    const unsigned bh1 = (ni & 1) ? Bfh[np].w : Bfh[np].y;
                    const unsigned bl0 = (ni & 1) ? Bfl[np].z : Bfl[np].x;
                    const unsigned bl1 = (ni & 1) ? Bfl[np].w : Bfl[np].y;
                    mma_bf16(acc[mi][ni], Afh[mi], bh0, bh1);
                    mma_bf16(acc[mi][ni], Afh[mi], bl0, bl1);
                    mma_bf16(acc[mi][ni], Afl[mi], bh0, bh1);
                }
        }
        buf = (buf == 2) ? 0 : buf + 1;
        nbuf = (nbuf == 2) ? 0 : nbuf + 1;
    }

    const int rbase = bm + warp_m * 64 + (lane >> 2);
    const int cbase = bn + warp_n * 32 + (lane & 3) * 2;
#pragma unroll
    for (int ni = 0; ni < 4; ni++) {
        const int c = cbase + ni * 8;
        if (MODE == 2) {
#pragma unroll
            for (int mi = 0; mi < 4; mi++) {
#pragma unroll
                for (int half = 0; half < 2; half++) {
                    const int r = rbase + mi * 16 + half * 8;
                    *(float2*)&Cout[(size_t)r * N + c] =
                        make_float2(acc[mi][ni][half * 2], acc[mi][ni][half * 2 + 1]);
                }
            }
        } else {
            const int seg = c >> 10;
            const int cc = c & 1023;
            const int h = cc >> 6, d0 = cc & 63;
            float* dstb = (seg == 0) ? g_q : (seg == 1) ? g_k : g_v;
#pragma unroll
            for (int mi = 0; mi < 4; mi++) {
#pragma unroll
                for (int half = 0; half < 2; half++) {
                    const int r = rbase + mi * 16 + half * 8;
                    const int b = r >> 11, t = r & 2047;
                    float v0 = acc[mi][ni][half * 2], v1 = acc[mi][ni][half * 2 + 1];
                    if (seg < 2) {
                        v0 = (v0 > 0.f) ? (v0 + 1.f) : expf(v0);
                        v1 = (v1 > 0.f) ? (v1 + 1.f) : expf(v1);
                    }
                    const size_t idx = ((size_t)(b * Hq + h) * Tq + t) * Dq + d0;
                    *(float2*)&dstb[idx] = make_float2(v0, v1);
                }
            }
        }
    }
}

// ---------------- per-chunk K^T V sums + k sums ------------------------------
__global__ __launch_bounds__(256)
void chunk_sums_kernel()
{
    const int c  = blockIdx.x;
    const int bh = blockIdx.y;
    const int tid = threadIdx.x;
    const int i0 = (tid >> 4) << 2;
    const int j0 = (tid & 15) << 2;
    const bool zowner = ((tid & 15) == 0);

    const float* kb = g_k + ((size_t)bh * Tq + c * LCHUNK) * Dq;
    const float* vb = g_v + ((size_t)bh * Tq + c * LCHUNK) * Dq;

    __shared__ float ks[32][64];
    __shared__ float vs[32][64];

    float s[4][4];
#pragma unroll
    for (int a = 0; a < 4; a++)
#pragma unroll
        for (int b = 0; b < 4; b++) s[a][b] = 0.f;
    float z[4] = {0.f, 0.f, 0.f, 0.f};

    for (int t0 = 0; t0 < LCHUNK; t0 += 32) {
#pragma unroll
        for (int l = 0; l < 2; l++) {
            const int f = tid * 2 + l;
            const int rr = f >> 4, cc4 = (f & 15) << 2;
            *(float4*)&ks[rr][cc4] = *(const float4*)(kb + (size_t)(t0 + rr) * 64 + cc4);
            *(float4*)&vs[rr][cc4] = *(const float4*)(vb + (size_t)(t0 + rr) * 64 + cc4);
        }
        __syncthreads();
#pragma unroll 8
        for (int tt = 0; tt < 32; tt++) {
            float kr[4], vr[4];
            *(float4*)kr = *(const float4*)&ks[tt][i0];
            *(float4*)vr = *(const float4*)&vs[tt][j0];
#pragma unroll
            for (int a = 0; a < 4; a++)
#pragma unroll
                for (int b = 0; b < 4; b++)
                    s[a][b] = fmaf(kr[a], vr[b], s[a][b]);
            if (zowner) {
#pragma unroll
                for (int a = 0; a < 4; a++) z[a] += kr[a];
            }
        }
        __syncthreads();
    }

    float* Sp = g_Sc + ((size_t)bh * NCHUNK + c) * (Dq * Dq);
#pragma unroll
    for (int a = 0; a < 4; a++)
        *(float4*)&Sp[(i0 + a) * Dq + j0] = make_float4(s[a][0], s[a][1], s[a][2], s[a][3]);
    if (zowner) {
        float* zp = g_zc + ((size_t)bh * NCHUNK + c) * Dq;
#pragma unroll
        for (int a = 0; a < 4; a++) zp[i0 + a] = z[a];
    }
}

// ---------------- exclusive scan over chunks ---------------------------------
__global__ __launch_bounds__(256)
void scan_kernel()
{
    const int bh = blockIdx.x;
    const int tid = threadIdx.x;
    const size_t base = (size_t)bh * NCHUNK;

    float run[16];
#pragma unroll
    for (int l = 0; l < 16; l++) run[l] = 0.f;
    float zrun = 0.f;

    for (int c = 0; c < NCHUNK; c++) {
        float*       sp = g_Sp + (base + c) * (Dq * Dq) + tid * 16;
        const float* sc = g_Sc + (base + c) * (Dq * Dq) + tid * 16;
#pragma unroll
        for (int l = 0; l < 16; l++) {
            sp[l] = run[l];
            run[l] += sc[l];
        }
        if (tid < Dq) {
            g_zp[(base + c) * Dq + tid] = zrun;
            zrun += g_zc[(base + c) * Dq + tid];
        }
    }
}

// ---------------- per-chunk attention (half-chunk blocks) --------------------
// grid (2*NCHUNK, BH): blockIdx.x = c*2 + half; block handles 64 q-rows.
// smem (floats): Qs 4096 | Ks 8448 | Asm 8192 | Ss 4096 | zs 64 | dens 64
#define AT_QS 0
#define AT_KS 4096
#define AT_A  12544
#define AT_S  20736
#define AT_Z  24832
#define AT_D  24896
#define AT_TOTAL 24960
#define AT_BYTES (AT_TOTAL * 4)   // 99840

__global__ __launch_bounds__(256)
void attn_kernel()
{
    extern __shared__ float sm[];
    float* Qs   = sm + AT_QS;     // [64][64] rows r0..r0+63
    float* Ks   = sm + AT_KS;     // K^T [d][s] stride 132; later V [s][64]
    float* Asm  = sm + AT_A;      // [64][128]
    float* Ss   = sm + AT_S;      // [d][64]
    float* zs   = sm + AT_Z;
    float* dens = sm + AT_D;

    const int c    = blockIdx.x >> 1;
    const int half = blockIdx.x & 1;
    const int bh   = blockIdx.y;
    const int tid  = threadIdx.x;
    const int r0   = half << 6;          // 0 or 64
    const int SEND = r0 + 64;            // K/V rows needed
    const size_t coff = ((size_t)bh * Tq + c * LCHUNK) * Dq;
    const size_t qoff = coff + (size_t)r0 * Dq;
    const size_t soff = ((size_t)bh * NCHUNK + c) * (Dq * Dq);

    for (int f = tid; f < 1024; f += 256) {
        const int t = f >> 4, d4 = (f & 15) << 2;
        *(float4*)&Qs[t * 64 + d4] = *(const float4*)(g_q + qoff + (size_t)t * 64 + d4);
    }
    for (int f = tid; f < SEND * 16; f += 256) {
        const int d  = f & 63;
        const int t0 = (f >> 6) << 2;
        const float x0 = g_k[coff + (size_t)(t0 + 0) * 64 + d];
        const float x1 = g_k[coff + (size_t)(t0 + 1) * 64 + d];
        const float x2 = g_k[coff + (size_t)(t0 + 2) * 64 + d];
        const float x3 = g_k[coff + (size_t)(t0 + 3) * 64 + d];
        *(float4*)&Ks[d * 132 + t0] = make_float4(x0, x1, x2, x3);
    }
    for (int f = tid; f < 1024; f += 256)
        *(float4*)&Ss[f * 4] = *(const float4*)(g_Sp + soff + f * 4);
    if (tid < Dq) zs[tid] = g_zp[((size_t)bh * NCHUNK + c) * Dq + tid];
    __syncthreads();

    if (tid < 64) {
        float acc = EPSq;
#pragma unroll
        for (int d0 = 0; d0 < 64; d0 += 4) {
            float4 q4 = *(const float4*)&Qs[tid * 64 + d0];
            float4 z4 = *(const float4*)&zs[d0];
            acc += q4.x * z4.x + q4.y * z4.y + q4.z * z4.z + q4.w * z4.w;
        }
        dens[tid] = acc;
    }
    __syncthreads();

    const int trow = (tid >> 4) << 2;    // 4 local rows per thread

    // Stage 1: A = Q K^T over s in [0, SEND), causal mask, rowsums
    if (half) {
        const int tcol = (tid & 15) << 3;   // 8 cols
        float a1[4][8];
#pragma unroll
        for (int i = 0; i < 4; i++)
#pragma unroll
            for (int j = 0; j < 8; j++) a1[i][j] = 0.f;
        for (int d0 = 0; d0 < 64; d0 += 4) {
            float kr[4][8];
#pragma unroll
            for (int l = 0; l < 4; l++) {
                *(float4*)(&kr[l][0]) = *(const float4*)&Ks[(d0 + l) * 132 + tcol];
                *(float4*)(&kr[l][4]) = *(const float4*)&Ks[(d0 + l) * 132 + tcol + 4];
            }
#pragma unroll
            for (int i = 0; i < 4; i++) {
                float4 q4 = *(const float4*)&Qs[(trow + i) * 64 + d0];
                const float qa[4] = {q4.x, q4.y, q4.z, q4.w};
#pragma unroll
                for (int l = 0; l < 4; l++)
#pragma unroll
                    for (int j = 0; j < 8; j++)
                        a1[i][j] = fmaf(qa[l], kr[l][j], a1[i][j]);
            }
        }
#pragma unroll
        for (int i = 0; i < 4; i++) {
            const int tl = trow + i;
            const int tg = r0 + tl;
            float rs = 0.f;
#pragma unroll
            for (int j = 0; j < 8; j++) {
                const int s = tcol + j;
                const float v = (s <= tg) ? a1[i][j] : 0.f;
                a1[i][j] = v;
                rs += v;
            }
            *(float4*)&Asm[tl * 128 + tcol]     = make_float4(a1[i][0], a1[i][1], a1[i][2], a1[i][3]);
            *(float4*)&Asm[tl * 128 + tcol + 4] = make_float4(a1[i][4], a1[i][5], a1[i][6], a1[i][7]);
            atomicAdd(&dens[tl], rs);
        }
    } else {
        const int tcol = (tid & 15) << 2;   // 4 cols (SEND=64)
        float a1[4][4];
#pragma unroll
        for (int i = 0; i < 4; i++)
#pragma unroll
            for (int j = 0; j < 4; j++) a1[i][j] = 0.f;
        for (int d0 = 0; d0 < 64; d0 += 4) {
            float kr[4][4];
#pragma unroll
            for (int l = 0; l < 4; l++)
                *(float4*)(&kr[l][0]) = *(const float4*)&Ks[(d0 + l) * 132 + tcol];
#pragma unroll
            for (int i = 0; i < 4; i++) {
                float4 q4 = *(const float4*)&Qs[(trow + i) * 64 + d0];
                const float qa[4] = {q4.x, q4.y, q4.z, q4.w};
#pragma unroll
                for (int l = 0; l < 4; l++)
#pragma unroll
                    for (int j = 0; j < 4; j++)
                        a1[i][j] = fmaf(qa[l], kr[l][j], a1[i][j]);
            }
        }
#pragma unroll
        for (int i = 0; i < 4; i++) {
            const int tl = trow + i;
            float rs = 0.f;
#pragma unroll
            for (int j = 0; j < 4; j++) {
                const int s = tcol + j;
                const float v = (s <= tl) ? a1[i][j] : 0.f;
                a1[i][j] = v;
                rs += v;
            }
            *(float4*)&Asm[tl * 128 + tcol] = make_float4(a1[i][0], a1[i][1], a1[i][2], a1[i][3]);
            atomicAdd(&dens[tl], rs);
        }
    }
    __syncthreads();

    // V rows [0, SEND) into Ks buffer (row-major [s][64])
    for (int f = tid; f < SEND * 16; f += 256)
        *(float4*)&Ks[f * 4] = *(const float4*)(g_v + coff + f * 4);
    __syncthreads();

    // Stage 2: y = A @ V + Q @ S, divide, write bf16 hi/lo
    const int jc = (tid & 15) << 2;
    float a2[4][4];
#pragma unroll
    for (int i = 0; i < 4; i++)
#pragma unroll
        for (int j = 0; j < 4; j++) a2[i][j] = 0.f;

    for (int s0 = 0; s0 < SEND; s0 += 4) {
        float vr[4][4];
#pragma unroll
        for (int l = 0; l < 4; l++)
            *(float4*)vr[l] = *(const float4*)&Ks[(s0 + l) * 64 + jc];
#pragma unroll
        for (int i = 0; i < 4; i++) {
            float4 av = *(const float4*)&Asm[(trow + i) * 128 + s0];
            const float aa[4] = {av.x, av.y, av.z, av.w};
#pragma unroll
            for (int l = 0; l < 4; l++)
#pragma unroll
                for (int j = 0; j < 4; j++)
                    a2[i][j] = fmaf(aa[l], vr[l][j], a2[i][j]);
        }
    }
    for (int d0 = 0; d0 < 64; d0 += 4) {
        float sr[4][4];
#pragma unroll
        for (int l = 0; l < 4; l++)
            *(float4*)sr[l] = *(const float4*)&Ss[(d0 + l) * 64 + jc];
#pragma unroll
        for (int i = 0; i < 4; i++) {
            float4 q4 = *(const float4*)&Qs[(trow + i) * 64 + d0];
            const float qa[4] = {q4.x, q4.y, q4.z, q4.w};
#pragma unroll
            for (int l = 0; l < 4; l++)
#pragma unroll
                for (int j = 0; j < 4; j++)
                    a2[i][j] = fmaf(qa[l], sr[l][j], a2[i][j]);
        }
    }

    const int b = bh >> 4, h = bh & 15;
#pragma unroll
    for (int i = 0; i < 4; i++) {
        const int tl = trow + i;
        const float inv = 1.0f / dens[tl];
        const size_t row = (size_t)b * Tq + c * LCHUNK + r0 + tl;
        const size_t idx = row * Cq + h * 64 + jc;
        float o0 = a2[i][0] * inv, o1 = a2[i][1] * inv;
        float o2 = a2[i][2] * inv, o3 = a2[i][3] * inv;
        __nv_bfloat16 h0 = __float2bfloat16(o0), h1 = __float2bfloat16(o1);
        __nv_bfloat16 h2 = __float2bfloat16(o2), h3 = __float2bfloat16(o3);
        __nv_bfloat16 l0 = __float2bfloat16(o0 - __bfloat162float(h0));
        __nv_bfloat16 l1 = __float2bfloat16(o1 - __bfloat162float(h1));
        __nv_bfloat16 l2 = __float2bfloat16(o2 - __bfloat162float(h2));
        __nv_bfloat16 l3 = __float2bfloat16(o3 - __bfloat162float(h3));
        uint2 uh, ul;
        uh.x = ((unsigned)__bfloat16_as_ushort(h1) << 16) | __bfloat16_as_ushort(h0);
        uh.y = ((unsigned)__bfloat16_as_ushort(h3) << 16) | __bfloat16_as_ushort(h2);
        ul.x = ((unsigned)__bfloat16_as_ushort(l1) << 16) | __bfloat16_as_ushort(l0);
        ul.y = ((unsigned)__bfloat16_as_ushort(l3) << 16) | __bfloat16_as_ushort(l2);
        *(uint2*)&g_yh[idx] = uh;
        *(uint2*)&g_yl[idx] = ul;
    }
}

// ---------------- launch -----------------------------------------------------
extern "C" void kernel_launch(void* const* d_in, const int* in_sizes, int n_in,
                              void* d_out, int out_size)
{
    const float* x      = (const float*)d_in[0];
    const float* w_attn = (const float*)d_in[1];
    const float* w_proj = (const float*)d_in[2];
    float* out = (float*)d_out;

    cudaFuncSetAttribute(attn_kernel, cudaFuncAttributeMaxDynamicSharedMemorySize, AT_BYTES);
    cudaFuncSetAttribute(mma_gemm<1>, cudaFuncAttributeMaxDynamicSharedMemorySize, GEMM_SMEM);
    cudaFuncSetAttribute(mma_gemm<2>, cudaFuncAttributeMaxDynamicSharedMemorySize, GEMM_SMEM);

    __nv_bfloat16 *xh, *xl, *wah, *wal, *wph, *wpl, *yh, *yl;
    cudaGetSymbolAddress((void**)&xh,  g_xh);
    cudaGetSymbolAddress((void**)&xl,  g_xl);
    cudaGetSymbolAddress((void**)&wah, g_wah);
    cudaGetSymbolAddress((void**)&wal, g_wal);
    cudaGetSymbolAddress((void**)&wph, g_wph);
    cudaGetSymbolAddress((void**)&wpl, g_wpl);
    cudaGetSymbolAddress((void**)&yh,  g_yh);
    cudaGetSymbolAddress((void**)&yl,  g_yl);

    split_kernel<<<(Mrows * Cq / 4 + 255) / 256, 256>>>(x, xh, xl, Mrows * Cq / 4);
    split_kernel<<<(Cq * 3 * Cq / 4 + 255) / 256, 256>>>(w_attn, wah, wal, Cq * 3 * Cq / 4);
    split_kernel<<<(Cq * Cq / 4 + 255) / 256, 256>>>(w_proj, wph, wpl, Cq * Cq / 4);

    mma_gemm<1><<<dim3(3 * Cq / 128, Mrows / 128), 256, GEMM_SMEM>>>(
        xh, xl, wah, wal, nullptr, 3 * Cq);
    chunk_sums_kernel<<<dim3(NCHUNK, BHq), 256>>>();
    scan_kernel<<<BHq, 256>>>();
    attn_kernel<<<dim3(2 * NCHUNK, BHq), 256, AT_BYTES>>>();
    mma_gemm<2><<<dim3(Cq / 128, Mrows / 128), 256, GEMM_SMEM>>>(
        yh, yl, wph, wpl, out, Cq);
}

// round 5
// speedup vs baseline: 1.4702x; 1.4702x over previous
#include <cuda_runtime.h>
#include <cuda_bf16.h>
#include <math.h>

// Problem constants
#define Bq 2
#define Tq 2048
#define Cq 1024
#define Hq 16
#define Dq 64
#define NCHUNK 16
#define LCHUNK 128
#define BHq (Bq * Hq)       // 32
#define Mrows (Bq * Tq)     // 4096
#define EPSq 1e-6f

// ---------------- scratch (device globals: no allocs allowed) ----------------
__device__ float g_q[(size_t)BHq * Tq * Dq];
__device__ float g_k[(size_t)BHq * Tq * Dq];
__device__ float g_v[(size_t)BHq * Tq * Dq];
__device__ float g_Sc[(size_t)BHq * NCHUNK * Dq * Dq];
__device__ float g_Sp[(size_t)BHq * NCHUNK * Dq * Dq];
__device__ float g_zc[(size_t)BHq * NCHUNK * Dq];
__device__ float g_zp[(size_t)BHq * NCHUNK * Dq];

__device__ __align__(16) __nv_bfloat16 g_xh[(size_t)Mrows * Cq];
__device__ __align__(16) __nv_bfloat16 g_xl[(size_t)Mrows * Cq];
__device__ __align__(16) __nv_bfloat16 g_wah[(size_t)Cq * 3 * Cq];
__device__ __align__(16) __nv_bfloat16 g_wal[(size_t)Cq * 3 * Cq];
__device__ __align__(16) __nv_bfloat16 g_wph[(size_t)Cq * Cq];
__device__ __align__(16) __nv_bfloat16 g_wpl[(size_t)Cq * Cq];
__device__ __align__(16) __nv_bfloat16 g_yh[(size_t)Mrows * Cq];
__device__ __align__(16) __nv_bfloat16 g_yl[(size_t)Mrows * Cq];

// ---------------- fp32 -> bf16 hi/lo split -----------------------------------
__global__ __launch_bounds__(256)
void split_kernel(const float* __restrict__ in, __nv_bfloat16* __restrict__ hi,
                  __nv_bfloat16* __restrict__ lo, int n4)
{
    const int i = blockIdx.x * 256 + threadIdx.x;
    if (i >= n4) return;
    float4 v = ((const float4*)in)[i];
    __nv_bfloat16 h0 = __float2bfloat16(v.x);
    __nv_bfloat16 h1 = __float2bfloat16(v.y);
    __nv_bfloat16 h2 = __float2bfloat16(v.z);
    __nv_bfloat16 h3 = __float2bfloat16(v.w);
    __nv_bfloat16 l0 = __float2bfloat16(v.x - __bfloat162float(h0));
    __nv_bfloat16 l1 = __float2bfloat16(v.y - __bfloat162float(h1));
    __nv_bfloat16 l2 = __float2bfloat16(v.z - __bfloat162float(h2));
    __nv_bfloat16 l3 = __float2bfloat16(v.w - __bfloat162float(h3));
    uint2 uh, ul;
    uh.x = ((unsigned)__bfloat16_as_ushort(h1) << 16) | __bfloat16_as_ushort(h0);
    uh.y = ((unsigned)__bfloat16_as_ushort(h3) << 16) | __bfloat16_as_ushort(h2);
    ul.x = ((unsigned)__bfloat16_as_ushort(l1) << 16) | __bfloat16_as_ushort(l0);
    ul.y = ((unsigned)__bfloat16_as_ushort(l3) << 16) | __bfloat16_as_ushort(l2);
    ((uint2*)hi)[i] = uh;
    ((uint2*)lo)[i] = ul;
}

// ---------------- MMA helpers ------------------------------------------------
__device__ __forceinline__ void ldsm_x4(uint4& r, unsigned addr) {
    asm volatile("ldmatrix.sync.aligned.m8n8.x4.shared.b16 {%0,%1,%2,%3}, [%4];"
                 : "=r"(r.x), "=r"(r.y), "=r"(r.z), "=r"(r.w) : "r"(addr));
}
__device__ __forceinline__ void ldsm_x4t(uint4& r, unsigned addr) {
    asm volatile("ldmatrix.sync.aligned.m8n8.x4.trans.shared.b16 {%0,%1,%2,%3}, [%4];"
                 : "=r"(r.x), "=r"(r.y), "=r"(r.z), "=r"(r.w) : "r"(addr));
}
__device__ __forceinline__ void mma_bf16(float c[4], const uint4& a, unsigned b0, unsigned b1) {
    asm volatile("mma.sync.aligned.m16n8k16.row.col.f32.bf16.bf16.f32 "
                 "{%0,%1,%2,%3},{%4,%5,%6,%7},{%8,%9},{%0,%1,%2,%3};"
                 : "+f"(c[0]), "+f"(c[1]), "+f"(c[2]), "+f"(c[3])
                 : "r"(a.x), "r"(a.y), "r"(a.z), "r"(a.w), "r"(b0), "r"(b1));
}
__device__ __forceinline__ void cp16(unsigned s, const void* g) {
    asm volatile("cp.async.cg.shared.global [%0], [%1], 16;\n" :: "r"(s), "l"(g));
}

// ---------------- bf16-split tensor-core GEMM (round-3 proven version) -------
// 2-stage double buffer, static (it&1) indexing, issue after compute.
#define STAGE_BYTES 32768    // Ah 8K | Al 8K | Bh 8K | Bl 8K
#define GEMM_SMEM   (2 * STAGE_BYTES)

template <int MODE>
__global__ __launch_bounds__(256)
void mma_gemm(const __nv_bfloat16* __restrict__ Ah, const __nv_bfloat16* __restrict__ Al,
              const __nv_bfloat16* __restrict__ Bh, const __nv_bfloat16* __restrict__ Bl,
              float* __restrict__ Cout, int N)
{
    constexpr int K = 1024;
    constexpr int NITER = K / 32;
    extern __shared__ char smem[];
    const unsigned sbase = (unsigned)__cvta_generic_to_shared(smem);

    const int tid = threadIdx.x;
    const int lane = tid & 31, wid = tid >> 5;
    const int warp_m = wid >> 2, warp_n = wid & 3;
    const int bm = blockIdx.y * 128, bn = blockIdx.x * 128;

    int sA[2], sB[2], gAr[2], gAc[2], gBr[2], gBc[2];
#pragma unroll
    for (int j = 0; j < 2; j++) {
        const int f = tid + j * 256;
        const int ar = f >> 2, ac = f & 3;
        sA[j] = (ar * 4 + (ac ^ ((ar >> 1) & 3))) * 16;
        gAr[j] = ar; gAc[j] = ac * 8;
        const int br = f >> 4, bg = f & 15;
        sB[j] = (br * 16 + ((bg & 8) | ((bg & 7) ^ (br & 7)))) * 16;
        gBr[j] = br; gBc[j] = bg * 8;
    }

    const int arow_l = warp_m * 64 + (lane & 15);
    const int aghalf = (lane >> 4) & 1;
    int aOff[4][2];
#pragma unroll
    for (int mi = 0; mi < 4; mi++) {
        const int row = arow_l + mi * 16;
        const int rsw = (row >> 1) & 3;
#pragma unroll
        for (int kx = 0; kx < 2; kx++) {
            const int c = kx * 2 + aghalf;
            aOff[mi][kx] = (row * 4 + (c ^ rsw)) * 16;
        }
    }
    const int bk_l = (lane & 7) + ((lane >> 3) & 1) * 8;
    const int gadd = lane >> 4;
    const int klow = bk_l & 7;
    int bOff[2][2];
#pragma unroll
    for (int kx = 0; kx < 2; kx++) {
        const int k = kx * 16 + bk_l;
#pragma unroll
        for (int np = 0; np < 2; np++) {
            const int g = warp_n * 4 + np * 2 + gadd;
            bOff[kx][np] = (k * 16 + ((g & 8) | ((g & 7) ^ klow))) * 16;
        }
    }

    float acc[4][4][4];
#pragma unroll
    for (int mi = 0; mi < 4; mi++)
#pragma unroll
        for (int ni = 0; ni < 4; ni++)
#pragma unroll
            for (int r = 0; r < 4; r++) acc[mi][ni][r] = 0.f;

    auto issue = [&](int stage, int k0) {
        const unsigned st = sbase + stage * STAGE_BYTES;
#pragma unroll
        for (int j = 0; j < 2; j++) {
            const size_t aoff = (size_t)(bm + gAr[j]) * K + k0 + gAc[j];
            const size_t boff = (size_t)(k0 + gBr[j]) * N + bn + gBc[j];
            cp16(st + sA[j],         Ah + aoff);
            cp16(st + 8192 + sA[j],  Al + aoff);
            cp16(st + 16384 + sB[j], Bh + boff);
            cp16(st + 24576 + sB[j], Bl + boff);
        }
        asm volatile("cp.async.commit_group;");
    };

    issue(0, 0);
    issue(1, 32);

    for (int it = 0; it < NITER; it++) {
        asm volatile("cp.async.wait_group 1;");
        __syncthreads();
        const unsigned st = sbase + (it & 1) * STAGE_BYTES;
#pragma unroll
        for (int kx = 0; kx < 2; kx++) {
            uint4 Afh[4], Afl[4], Bfh[2], Bfl[2];
#pragma unroll
            for (int mi = 0; mi < 4; mi++) {
                ldsm_x4(Afh[mi], st + aOff[mi][kx]);
                ldsm_x4(Afl[mi], st + 8192 + aOff[mi][kx]);
            }
#pragma unroll
            for (int np = 0; np < 2; np++) {
                ldsm_x4t(Bfh[np], st + 16384 + bOff[kx][np]);
                ldsm_x4t(Bfl[np], st + 24576 + bOff[kx][np]);
            }
#pragma unroll
            for (int mi = 0; mi < 4; mi++)
#pragma unroll
                for (int ni = 0; ni < 4; ni++) {
                    const int np = ni >> 1;
                    const unsigned bh0 = (ni & 1) ? Bfh[np].z : Bfh[np].x;
                    const unsigned bh1 = (ni & 1) ? Bfh[np].w : Bfh[np].y;
                    const unsigned bl0 = (ni & 1) ? Bfl[np].z : Bfl[np].x;
                    const unsigned bl1 = (ni & 1) ? Bfl[np].w : Bfl[np].y;
                    mma_bf16(acc[mi][ni], Afh[mi], bh0, bh1);
                    mma_bf16(acc[mi][ni], Afh[mi], bl0, bl1);
                    mma_bf16(acc[mi][ni], Afl[mi], bh0, bh1);
                }
        }
        __syncthreads();
        if (it + 2 < NITER) issue(it & 1, (it + 2) * 32);
        else asm volatile("cp.async.commit_group;");
    }

    const int rbase = bm + warp_m * 64 + (lane >> 2);
    const int cbase = bn + warp_n * 32 + (lane & 3) * 2;
#pragma unroll
    for (int ni = 0; ni < 4; ni++) {
        const int c = cbase + ni * 8;
        if (MODE == 2) {
#pragma unroll
            for (int mi = 0; mi < 4; mi++) {
#pragma unroll
                for (int half = 0; half < 2; half++) {
                    const int r = rbase + mi * 16 + half * 8;
                    *(float2*)&Cout[(size_t)r * N + c] =
                        make_float2(acc[mi][ni][half * 2], acc[mi][ni][half * 2 + 1]);
                }
            }
        } else {
            const int seg = c >> 10;
            const int cc = c & 1023;
            const int h = cc >> 6, d0 = cc & 63;
            float* dstb = (seg == 0) ? g_q : (seg == 1) ? g_k : g_v;
#pragma unroll
            for (int mi = 0; mi < 4; mi++) {
#pragma unroll
                for (int half = 0; half < 2; half++) {
                    const int r = rbase + mi * 16 + half * 8;
                    const int b = r >> 11, t = r & 2047;
                    float v0 = acc[mi][ni][half * 2], v1 = acc[mi][ni][half * 2 + 1];
                    if (seg < 2) {
                        v0 = (v0 > 0.f) ? (v0 + 1.f) : expf(v0);
                        v1 = (v1 > 0.f) ? (v1 + 1.f) : expf(v1);
                    }
                    const size_t idx = ((size_t)(b * Hq + h) * Tq + t) * Dq + d0;
                    *(float2*)&dstb[idx] = make_float2(v0, v1);
                }
            }
        }
    }
}

// ---------------- per-chunk K^T V sums + k sums ------------------------------
__global__ __launch_bounds__(256)
void chunk_sums_kernel()
{
    const int c  = blockIdx.x;
    const int bh = blockIdx.y;
    const int tid = threadIdx.x;
    const int i0 = (tid >> 4) << 2;
    const int j0 = (tid & 15) << 2;
    const bool zowner = ((tid & 15) == 0);

    const float* kb = g_k + ((size_t)bh * Tq + c * LCHUNK) * Dq;
    const float* vb = g_v + ((size_t)bh * Tq + c * LCHUNK) * Dq;

    __shared__ float ks[32][64];
    __shared__ float vs[32][64];

    float s[4][4];
#pragma unroll
    for (int a = 0; a < 4; a++)
#pragma unroll
        for (int b = 0; b < 4; b++) s[a][b] = 0.f;
    float z[4] = {0.f, 0.f, 0.f, 0.f};

    for (int t0 = 0; t0 < LCHUNK; t0 += 32) {
#pragma unroll
        for (int l = 0; l < 2; l++) {
            const int f = tid * 2 + l;
            const int rr = f >> 4, cc4 = (f & 15) << 2;
            *(float4*)&ks[rr][cc4] = *(const float4*)(kb + (size_t)(t0 + rr) * 64 + cc4);
            *(float4*)&vs[rr][cc4] = *(const float4*)(vb + (size_t)(t0 + rr) * 64 + cc4);
        }
        __syncthreads();
#pragma unroll 8
        for (int tt = 0; tt < 32; tt++) {
            float kr[4], vr[4];
            *(float4*)kr = *(const float4*)&ks[tt][i0];
            *(float4*)vr = *(const float4*)&vs[tt][j0];
#pragma unroll
            for (int a = 0; a < 4; a++)
#pragma unroll
                for (int b = 0; b < 4; b++)
                    s[a][b] = fmaf(kr[a], vr[b], s[a][b]);
            if (zowner) {
#pragma unroll
                for (int a = 0; a < 4; a++) z[a] += kr[a];
            }
        }
        __syncthreads();
    }

    float* Sp = g_Sc + ((size_t)bh * NCHUNK + c) * (Dq * Dq);
#pragma unroll
    for (int a = 0; a < 4; a++)
        *(float4*)&Sp[(i0 + a) * Dq + j0] = make_float4(s[a][0], s[a][1], s[a][2], s[a][3]);
    if (zowner) {
        float* zp = g_zc + ((size_t)bh * NCHUNK + c) * Dq;
#pragma unroll
        for (int a = 0; a < 4; a++) zp[i0 + a] = z[a];
    }
}

// ---------------- exclusive scan over chunks ---------------------------------
__global__ __launch_bounds__(256)
void scan_kernel()
{
    const int bh = blockIdx.x;
    const int tid = threadIdx.x;
    const size_t base = (size_t)bh * NCHUNK;

    float run[16];
#pragma unroll
    for (int l = 0; l < 16; l++) run[l] = 0.f;
    float zrun = 0.f;

    for (int c = 0; c < NCHUNK; c++) {
        float*       sp = g_Sp + (base + c) * (Dq * Dq) + tid * 16;
        const float* sc = g_Sc + (base + c) * (Dq * Dq) + tid * 16;
#pragma unroll
        for (int l = 0; l < 16; l++) {
            sp[l] = run[l];
            run[l] += sc[l];
        }
        if (tid < Dq) {
            g_zp[(base + c) * Dq + tid] = zrun;
            zrun += g_zc[(base + c) * Dq + tid];
        }
    }
}

// ---------------- per-chunk attention (half-chunk blocks) --------------------
#define AT_QS 0
#define AT_KS 4096
#define AT_A  12544
#define AT_S  20736
#define AT_Z  24832
#define AT_D  24896
#define AT_TOTAL 24960
#define AT_BYTES (AT_TOTAL * 4)   // 99840

__global__ __launch_bounds__(256)
void attn_kernel()
{
    extern __shared__ float sm[];
    float* Qs   = sm + AT_QS;
    float* Ks   = sm + AT_KS;
    float* Asm  = sm + AT_A;
    float* Ss   = sm + AT_S;
    float* zs   = sm + AT_Z;
    float* dens = sm + AT_D;

    const int c    = blockIdx.x >> 1;
    const int half = blockIdx.x & 1;
    const int bh   = blockIdx.y;
    const int tid  = threadIdx.x;
    const int r0   = half << 6;
    const int SEND = r0 + 64;
    const size_t coff = ((size_t)bh * Tq + c * LCHUNK) * Dq;
    const size_t qoff = coff + (size_t)r0 * Dq;
    const size_t soff = ((size_t)bh * NCHUNK + c) * (Dq * Dq);

    for (int f = tid; f < 1024; f += 256) {
        const int t = f >> 4, d4 = (f & 15) << 2;
        *(float4*)&Qs[t * 64 + d4] = *(const float4*)(g_q + qoff + (size_t)t * 64 + d4);
    }
    for (int f = tid; f < SEND * 16; f += 256) {
        const int d  = f & 63;
        const int t0 = (f >> 6) << 2;
        const float x0 = g_k[coff + (size_t)(t0 + 0) * 64 + d];
        const float x1 = g_k[coff + (size_t)(t0 + 1) * 64 + d];
        const float x2 = g_k[coff + (size_t)(t0 + 2) * 64 + d];
        const float x3 = g_k[coff + (size_t)(t0 + 3) * 64 + d];
        *(float4*)&Ks[d * 132 + t0] = make_float4(x0, x1, x2, x3);
    }
    for (int f = tid; f < 1024; f += 256)
        *(float4*)&Ss[f * 4] = *(const float4*)(g_Sp + soff + f * 4);
    if (tid < Dq) zs[tid] = g_zp[((size_t)bh * NCHUNK + c) * Dq + tid];
    __syncthreads();

    if (tid < 64) {
        float acc = EPSq;
#pragma unroll
        for (int d0 = 0; d0 < 64; d0 += 4) {
            float4 q4 = *(const float4*)&Qs[tid * 64 + d0];
            float4 z4 = *(const float4*)&zs[d0];
            acc += q4.x * z4.x + q4.y * z4.y + q4.z * z4.z + q4.w * z4.w;
        }
        dens[tid] = acc;
    }
    __syncthreads();

    const int trow = (tid >> 4) << 2;

    if (half) {
        const int tcol = (tid & 15) << 3;
        float a1[4][8];
#pragma unroll
        for (int i = 0; i < 4; i++)
#pragma unroll
            for (int j = 0; j < 8; j++) a1[i][j] = 0.f;
        for (int d0 = 0; d0 < 64; d0 += 4) {
            float kr[4][8];
#pragma unroll
            for (int l = 0; l < 4; l++) {
                *(float4*)(&kr[l][0]) = *(const float4*)&Ks[(d0 + l) * 132 + tcol];
                *(float4*)(&kr[l][4]) = *(const float4*)&Ks[(d0 + l) * 132 + tcol + 4];
            }
#pragma unroll
            for (int i = 0; i < 4; i++) {
                float4 q4 = *(const float4*)&Qs[(trow + i) * 64 + d0];
                const float qa[4] = {q4.x, q4.y, q4.z, q4.w};
#pragma unroll
                for (int l = 0; l < 4; l++)
#pragma unroll
                    for (int j = 0; j < 8; j++)
                        a1[i][j] = fmaf(qa[l], kr[l][j], a1[i][j]);
            }
        }
#pragma unroll
        for (int i = 0; i < 4; i++) {
            const int tl = trow + i;
            const int tg = r0 + tl;
            float rs = 0.f;
#pragma unroll
            for (int j = 0; j < 8; j++) {
                const int s = tcol + j;
                const float v = (s <= tg) ? a1[i][j] : 0.f;
                a1[i][j] = v;
                rs += v;
            }
            *(float4*)&Asm[tl * 128 + tcol]     = make_float4(a1[i][0], a1[i][1], a1[i][2], a1[i][3]);
            *(float4*)&Asm[tl * 128 + tcol + 4] = make_float4(a1[i][4], a1[i][5], a1[i][6], a1[i][7]);
            atomicAdd(&dens[tl], rs);
        }
    } else {
        const int tcol = (tid & 15) << 2;
        float a1[4][4];
#pragma unroll
        for (int i = 0; i < 4; i++)
#pragma unroll
            for (int j = 0; j < 4; j++) a1[i][j] = 0.f;
        for (int d0 = 0; d0 < 64; d0 += 4) {
            float kr[4][4];
#pragma unroll
            for (int l = 0; l < 4; l++)
                *(float4*)(&kr[l][0]) = *(const float4*)&Ks[(d0 + l) * 132 + tcol];
#pragma unroll
            for (int i = 0; i < 4; i++) {
                float4 q4 = *(const float4*)&Qs[(trow + i) * 64 + d0];
                const float qa[4] = {q4.x, q4.y, q4.z, q4.w};
#pragma unroll
                for (int l = 0; l < 4; l++)
#pragma unroll
                    for (int j = 0; j < 4; j++)
                        a1[i][j] = fmaf(qa[l], kr[l][j], a1[i][j]);
            }
        }
#pragma unroll
        for (int i = 0; i < 4; i++) {
            const int tl = trow + i;
            float rs = 0.f;
#pragma unroll
            for (int j = 0; j < 4; j++) {
                const int s = tcol + j;
                const float v = (s <= tl) ? a1[i][j] : 0.f;
                a1[i][j] = v;
                rs += v;
            }
            *(float4*)&Asm[tl * 128 + tcol] = make_float4(a1[i][0], a1[i][1], a1[i][2], a1[i][3]);
            atomicAdd(&dens[tl], rs);
        }
    }
    __syncthreads();

    for (int f = tid; f < SEND * 16; f += 256)
        *(float4*)&Ks[f * 4] = *(const float4*)(g_v + coff + f * 4);
    __syncthreads();

    const int jc = (tid & 15) << 2;
    float a2[4][4];
#pragma unroll
    for (int i = 0; i < 4; i++)
#pragma unroll
        for (int j = 0; j < 4; j++) a2[i][j] = 0.f;

    for (int s0 = 0; s0 < SEND; s0 += 4) {
        float vr[4][4];
#pragma unroll
        for (int l = 0; l < 4; l++)
            *(float4*)vr[l] = *(const float4*)&Ks[(s0 + l) * 64 + jc];
#pragma unroll
        for (int i = 0; i < 4; i++) {
            float4 av = *(const float4*)&Asm[(trow + i) * 128 + s0];
            const float aa[4] = {av.x, av.y, av.z, av.w};
#pragma unroll
            for (int l = 0; l < 4; l++)
#pragma unroll
                for (int j = 0; j < 4; j++)
                    a2[i][j] = fmaf(aa[l], vr[l][j], a2[i][j]);
        }
    }
    for (int d0 = 0; d0 < 64; d0 += 4) {
        float sr[4][4];
#pragma unroll
        for (int l = 0; l < 4; l++)
            *(float4*)sr[l] = *(const float4*)&Ss[(d0 + l) * 64 + jc];
#pragma unroll
        for (int i = 0; i < 4; i++) {
            float4 q4 = *(const float4*)&Qs[(trow + i) * 64 + d0];
            const float qa[4] = {q4.x, q4.y, q4.z, q4.w};
#pragma unroll
            for (int l = 0; l < 4; l++)
#pragma unroll
                for (int j = 0; j < 4; j++)
                    a2[i][j] = fmaf(qa[l], sr[l][j], a2[i][j]);
        }
    }

    const int b = bh >> 4, h = bh & 15;
#pragma unroll
    for (int i = 0; i < 4; i++) {
        const int tl = trow + i;
        const float inv = 1.0f / dens[tl];
        const size_t row = (size_t)b * Tq + c * LCHUNK + r0 + tl;
        const size_t idx = row * Cq + h * 64 + jc;
        float o0 = a2[i][0] * inv, o1 = a2[i][1] * inv;
        float o2 = a2[i][2] * inv, o3 = a2[i][3] * inv;
        __nv_bfloat16 h0 = __float2bfloat16(o0), h1 = __float2bfloat16(o1);
        __nv_bfloat16 h2 = __float2bfloat16(o2), h3 = __float2bfloat16(o3);
        __nv_bfloat16 l0 = __float2bfloat16(o0 - __bfloat162float(h0));
        __nv_bfloat16 l1 = __float2bfloat16(o1 - __bfloat162float(h1));
        __nv_bfloat16 l2 = __float2bfloat16(o2 - __bfloat162float(h2));
        __nv_bfloat16 l3 = __float2bfloat16(o3 - __bfloat162float(h3));
        uint2 uh, ul;
        uh.x = ((unsigned)__bfloat16_as_ushort(h1) << 16) | __bfloat16_as_ushort(h0);
        uh.y = ((unsigned)__bfloat16_as_ushort(h3) << 16) | __bfloat16_as_ushort(h2);
        ul.x = ((unsigned)__bfloat16_as_ushort(l1) << 16) | __bfloat16_as_ushort(l0);
        ul.y = ((unsigned)__bfloat16_as_ushort(l3) << 16) | __bfloat16_as_ushort(l2);
        *(uint2*)&g_yh[idx] = uh;
        *(uint2*)&g_yl[idx] = ul;
    }
}

// ---------------- launch -----------------------------------------------------
extern "C" void kernel_launch(void* const* d_in, const int* in_sizes, int n_in,
                              void* d_out, int out_size)
{
    const float* x      = (const float*)d_in[0];
    const float* w_attn = (const float*)d_in[1];
    const float* w_proj = (const float*)d_in[2];
    float* out = (float*)d_out;

    cudaFuncSetAttribute(attn_kernel, cudaFuncAttributeMaxDynamicSharedMemorySize, AT_BYTES);
    cudaFuncSetAttribute(mma_gemm<1>, cudaFuncAttributeMaxDynamicSharedMemorySize, GEMM_SMEM);
    cudaFuncSetAttribute(mma_gemm<2>, cudaFuncAttributeMaxDynamicSharedMemorySize, GEMM_SMEM);

    __nv_bfloat16 *xh, *xl, *wah, *wal, *wph, *wpl, *yh, *yl;
    cudaGetSymbolAddress((void**)&xh,  g_xh);
    cudaGetSymbolAddress((void**)&xl,  g_xl);
    cudaGetSymbolAddress((void**)&wah, g_wah);
    cudaGetSymbolAddress((void**)&wal, g_wal);
    cudaGetSymbolAddress((void**)&wph, g_wph);
    cudaGetSymbolAddress((void**)&wpl, g_wpl);
    cudaGetSymbolAddress((void**)&yh,  g_yh);
    cudaGetSymbolAddress((void**)&yl,  g_yl);

    split_kernel<<<(Mrows * Cq / 4 + 255) / 256, 256>>>(x, xh, xl, Mrows * Cq / 4);
    split_kernel<<<(Cq * 3 * Cq / 4 + 255) / 256, 256>>>(w_attn, wah, wal, Cq * 3 * Cq / 4);
    split_kernel<<<(Cq * Cq / 4 + 255) / 256, 256>>>(w_proj, wph, wpl, Cq * Cq / 4);

    mma_gemm<1><<<dim3(3 * Cq / 128, Mrows / 128), 256, GEMM_SMEM>>>(
        xh, xl, wah, wal, nullptr, 3 * Cq);
    chunk_sums_kernel<<<dim3(NCHUNK, BHq), 256>>>();
    scan_kernel<<<BHq, 256>>>();
    attn_kernel<<<dim3(2 * NCHUNK, BHq), 256, AT_BYTES>>>();
    mma_gemm<2><<<dim3(Cq / 128, Mrows / 128), 256, GEMM_SMEM>>>(
        yh, yl, wph, wpl, out, Cq);
}

// round 7
// speedup vs baseline: 1.5210x; 1.0345x over previous
#include <cuda_runtime.h>
#include <cuda_bf16.h>
#include <math.h>

// Problem constants
#define Bq 2
#define Tq 2048
#define Cq 1024
#define Hq 16
#define Dq 64
#define NCHUNK 16
#define LCHUNK 128
#define BHq (Bq * Hq)       // 32
#define Mrows (Bq * Tq)     // 4096
#define EPSq 1e-6f

// ---------------- scratch (device globals: no allocs allowed) ----------------
__device__ float g_q[(size_t)BHq * Tq * Dq];
__device__ float g_k[(size_t)BHq * Tq * Dq];
__device__ float g_v[(size_t)BHq * Tq * Dq];
__device__ float g_Sc[(size_t)BHq * NCHUNK * Dq * Dq];
__device__ float g_Sp[(size_t)BHq * NCHUNK * Dq * Dq];
__device__ float g_zc[(size_t)BHq * NCHUNK * Dq];
__device__ float g_zp[(size_t)BHq * NCHUNK * Dq];

__device__ __align__(16) __nv_bfloat16 g_xh[(size_t)Mrows * Cq];
__device__ __align__(16) __nv_bfloat16 g_xl[(size_t)Mrows * Cq];
__device__ __align__(16) __nv_bfloat16 g_wah[(size_t)Cq * 3 * Cq];
__device__ __align__(16) __nv_bfloat16 g_wal[(size_t)Cq * 3 * Cq];
__device__ __align__(16) __nv_bfloat16 g_wph[(size_t)Cq * Cq];
__device__ __align__(16) __nv_bfloat16 g_wpl[(size_t)Cq * Cq];
__device__ __align__(16) __nv_bfloat16 g_yh[(size_t)Mrows * Cq];
__device__ __align__(16) __nv_bfloat16 g_yl[(size_t)Mrows * Cq];

// ---------------- fp32 -> bf16 hi/lo split -----------------------------------
__global__ __launch_bounds__(256)
void split_kernel(const float* __restrict__ in, __nv_bfloat16* __restrict__ hi,
                  __nv_bfloat16* __restrict__ lo, int n4)
{
    const int i = blockIdx.x * 256 + threadIdx.x;
    if (i >= n4) return;
    float4 v = ((const float4*)in)[i];
    __nv_bfloat16 h0 = __float2bfloat16(v.x);
    __nv_bfloat16 h1 = __float2bfloat16(v.y);
    __nv_bfloat16 h2 = __float2bfloat16(v.z);
    __nv_bfloat16 h3 = __float2bfloat16(v.w);
    __nv_bfloat16 l0 = __float2bfloat16(v.x - __bfloat162float(h0));
    __nv_bfloat16 l1 = __float2bfloat16(v.y - __bfloat162float(h1));
    __nv_bfloat16 l2 = __float2bfloat16(v.z - __bfloat162float(h2));
    __nv_bfloat16 l3 = __float2bfloat16(v.w - __bfloat162float(h3));
    uint2 uh, ul;
    uh.x = ((unsigned)__bfloat16_as_ushort(h1) << 16) | __bfloat16_as_ushort(h0);
    uh.y = ((unsigned)__bfloat16_as_ushort(h3) << 16) | __bfloat16_as_ushort(h2);
    ul.x = ((unsigned)__bfloat16_as_ushort(l1) << 16) | __bfloat16_as_ushort(l0);
    ul.y = ((unsigned)__bfloat16_as_ushort(l3) << 16) | __bfloat16_as_ushort(l2);
    ((uint2*)hi)[i] = uh;
    ((uint2*)lo)[i] = ul;
}

// ---------------- MMA helpers ------------------------------------------------
__device__ __forceinline__ void ldsm_x4(uint4& r, unsigned addr) {
    asm volatile("ldmatrix.sync.aligned.m8n8.x4.shared.b16 {%0,%1,%2,%3}, [%4];"
                 : "=r"(r.x), "=r"(r.y), "=r"(r.z), "=r"(r.w) : "r"(addr));
}
__device__ __forceinline__ void ldsm_x4t(uint4& r, unsigned addr) {
    asm volatile("ldmatrix.sync.aligned.m8n8.x4.trans.shared.b16 {%0,%1,%2,%3}, [%4];"
                 : "=r"(r.x), "=r"(r.y), "=r"(r.z), "=r"(r.w) : "r"(addr));
}
__device__ __forceinline__ void mma_bf16(float c[4], const uint4& a, unsigned b0, unsigned b1) {
    asm volatile("mma.sync.aligned.m16n8k16.row.col.f32.bf16.bf16.f32 "
                 "{%0,%1,%2,%3},{%4,%5,%6,%7},{%8,%9},{%0,%1,%2,%3};"
                 : "+f"(c[0]), "+f"(c[1]), "+f"(c[2]), "+f"(c[3])
                 : "r"(a.x), "r"(a.y), "r"(a.z), "r"(a.w), "r"(b0), "r"(b1));
}
__device__ __forceinline__ void cp16(unsigned s, const void* g) {
    asm volatile("cp.async.cg.shared.global [%0], [%1], 16;\n" :: "r"(s), "l"(g));
}

// ---------------- bf16-split tensor-core GEMM, K-step 64 ---------------------
// 2-stage double buffer, static (it&1) indexing, issue after compute.
// Per stage: Ah 16K | Al 16K | Bh 16K | Bl 16K = 64KB.
#define STAGE_BYTES 65536
#define GEMM_SMEM   (2 * STAGE_BYTES)

template <int MODE>
__global__ __launch_bounds__(256)
void mma_gemm(const __nv_bfloat16* __restrict__ Ah, const __nv_bfloat16* __restrict__ Al,
              const __nv_bfloat16* __restrict__ Bh, const __nv_bfloat16* __restrict__ Bl,
              float* __restrict__ Cout, int N)
{
    constexpr int K = 1024;
    constexpr int KSTEP = 64;
    constexpr int NITER = K / KSTEP;     // 16
    extern __shared__ char smem[];
    const unsigned sbase = (unsigned)__cvta_generic_to_shared(smem);

    const int tid = threadIdx.x;
    const int lane = tid & 31, wid = tid >> 5;
    const int warp_m = wid >> 2, warp_n = wid & 3;
    const int bm = blockIdx.y * 128, bn = blockIdx.x * 128;

    // ---- gmem->smem store descriptors (4 granules each of A and B per thread)
    // A tile: 128 rows x 64 bf16 (8 granules/row), swizzle c ^ (row&7)
    // B tile:  64 rows x 128 bf16 (16 granules/row), swizzle (g&8)|((g&7)^(row&7))
    int sA[4], sB[4], gAr[4], gAc[4], gBr[4], gBc[4];
#pragma unroll
    for (int j = 0; j < 4; j++) {
        const int f = tid + j * 256;          // 0..1023
        const int ar = f >> 3, ac = f & 7;
        sA[j] = (ar * 8 + (ac ^ (ar & 7))) * 16;
        gAr[j] = ar; gAc[j] = ac * 8;
        const int br = f >> 4, bg = f & 15;
        sB[j] = (br * 16 + ((bg & 8) | ((bg & 7) ^ (br & 7)))) * 16;
        gBr[j] = br; gBc[j] = bg * 8;
    }

    // ---- ldmatrix read offsets (stage-invariant byte offsets)
    const int arow_l = warp_m * 64 + (lane & 15);
    const int aghalf = (lane >> 4) & 1;
    int aOff[4][4];
#pragma unroll
    for (int mi = 0; mi < 4; mi++) {
        const int row = arow_l + mi * 16;
        const int rsw = row & 7;
#pragma unroll
        for (int kx = 0; kx < 4; kx++) {
            const int c = kx * 2 + aghalf;    // granule col 0..7
            aOff[mi][kx] = (row * 8 + (c ^ rsw)) * 16;
        }
    }
    const int bk_l = (lane & 7) + ((lane >> 3) & 1) * 8;
    const int gadd = lane >> 4;
    const int klow = bk_l & 7;
    int bOff[4][2];
#pragma unroll
    for (int kx = 0; kx < 4; kx++) {
        const int k = kx * 16 + bk_l;
#pragma unroll
        for (int np = 0; np < 2; np++) {
            const int g = warp_n * 4 + np * 2 + gadd;
            bOff[kx][np] = (k * 16 + ((g & 8) | ((g & 7) ^ klow))) * 16;
        }
    }

    float acc[4][4][4];
#pragma unroll
    for (int mi = 0; mi < 4; mi++)
#pragma unroll
        for (int ni = 0; ni < 4; ni++)
#pragma unroll
            for (int r = 0; r < 4; r++) acc[mi][ni][r] = 0.f;

    auto issue = [&](int stage, int k0) {
        const unsigned st = sbase + stage * STAGE_BYTES;
#pragma unroll
        for (int j = 0; j < 4; j++) {
            const size_t aoff = (size_t)(bm + gAr[j]) * K + k0 + gAc[j];
            const size_t boff = (size_t)(k0 + gBr[j]) * N + bn + gBc[j];
            cp16(st + sA[j],         Ah + aoff);
            cp16(st + 16384 + sA[j], Al + aoff);
            cp16(st + 32768 + sB[j], Bh + boff);
            cp16(st + 49152 + sB[j], Bl + boff);
        }
        asm volatile("cp.async.commit_group;");
    };

    issue(0, 0);
    issue(1, KSTEP);

    for (int it = 0; it < NITER; it++) {
        asm volatile("cp.async.wait_group 1;");
        __syncthreads();
        const unsigned st = sbase + (it & 1) * STAGE_BYTES;
#pragma unroll
        for (int kx = 0; kx < 4; kx++) {
            uint4 Afh[4], Afl[4], Bfh[2], Bfl[2];
#pragma unroll
            for (int mi = 0; mi < 4; mi++) {
                ldsm_x4(Afh[mi], st + aOff[mi][kx]);
                ldsm_x4(Afl[mi], st + 16384 + aOff[mi][kx]);
            }
#pragma unroll
            for (int np = 0; np < 2; np++) {
                ldsm_x4t(Bfh[np], st + 32768 + bOff[kx][np]);
                ldsm_x4t(Bfl[np], st + 49152 + bOff[kx][np]);
            }
#pragma unroll
            for (int mi = 0; mi < 4; mi++)
#pragma unroll
                for (int ni = 0; ni < 4; ni++) {
                    const int np = ni >> 1;
                    const unsigned bh0 = (ni & 1) ? Bfh[np].z : Bfh[np].x;
                    const unsigned bh1 = (ni & 1) ? Bfh[np].w : Bfh[np].y;
                    const unsigned bl0 = (ni & 1) ? Bfl[np].z : Bfl[np].x;
                    const unsigned bl1 = (ni & 1) ? Bfl[np].w : Bfl[np].y;
                    mma_bf16(acc[mi][ni], Afh[mi], bh0, bh1);
                    mma_bf16(acc[mi][ni], Afh[mi], bl0, bl1);
                    mma_bf16(acc[mi][ni], Afl[mi], bh0, bh1);
                }
        }
        __syncthreads();
        if (it + 2 < NITER) issue(it & 1, (it + 2) * KSTEP);
        else asm volatile("cp.async.commit_group;");
    }

    const int rbase = bm + warp_m * 64 + (lane >> 2);
    const int cbase = bn + warp_n * 32 + (lane & 3) * 2;
#pragma unroll
    for (int ni = 0; ni < 4; ni++) {
        const int c = cbase + ni * 8;
        if (MODE == 2) {
#pragma unroll
            for (int mi = 0; mi < 4; mi++) {
#pragma unroll
                for (int half = 0; half < 2; half++) {
                    const int r = rbase + mi * 16 + half * 8;
                    *(float2*)&Cout[(size_t)r * N + c] =
                        make_float2(acc[mi][ni][half * 2], acc[mi][ni][half * 2 + 1]);
                }
            }
        } else {
            const int seg = c >> 10;
            const int cc = c & 1023;
            const int h = cc >> 6, d0 = cc & 63;
            float* dstb = (seg == 0) ? g_q : (seg == 1) ? g_k : g_v;
#pragma unroll
            for (int mi = 0; mi < 4; mi++) {
#pragma unroll
                for (int half = 0; half < 2; half++) {
                    const int r = rbase + mi * 16 + half * 8;
                    const int b = r >> 11, t = r & 2047;
                    float v0 = acc[mi][ni][half * 2], v1 = acc[mi][ni][half * 2 + 1];
                    if (seg < 2) {
                        v0 = (v0 > 0.f) ? (v0 + 1.f) : expf(v0);
                        v1 = (v1 > 0.f) ? (v1 + 1.f) : expf(v1);
                    }
                    const size_t idx = ((size_t)(b * Hq + h) * Tq + t) * Dq + d0;
                    *(float2*)&dstb[idx] = make_float2(v0, v1);
                }
            }
        }
    }
}

// ---------------- per-chunk K^T V sums + k sums ------------------------------
__global__ __launch_bounds__(256)
void chunk_sums_kernel()
{
    const int c  = blockIdx.x;
    const int bh = blockIdx.y;
    const int tid = threadIdx.x;
    const int i0 = (tid >> 4) << 2;
    const int j0 = (tid & 15) << 2;
    const bool zowner = ((tid & 15) == 0);

    const float* kb = g_k + ((size_t)bh * Tq + c * LCHUNK) * Dq;
    const float* vb = g_v + ((size_t)bh * Tq + c * LCHUNK) * Dq;

    __shared__ float ks[32][64];
    __shared__ float vs[32][64];

    float s[4][4];
#pragma unroll
    for (int a = 0; a < 4; a++)
#pragma unroll
        for (int b = 0; b < 4; b++) s[a][b] = 0.f;
    float z[4] = {0.f, 0.f, 0.f, 0.f};

    for (int t0 = 0; t0 < LCHUNK; t0 += 32) {
#pragma unroll
        for (int l = 0; l < 2; l++) {
            const int f = tid * 2 + l;
            const int rr = f >> 4, cc4 = (f & 15) << 2;
            *(float4*)&ks[rr][cc4] = *(const float4*)(kb + (size_t)(t0 + rr) * 64 + cc4);
            *(float4*)&vs[rr][cc4] = *(const float4*)(vb + (size_t)(t0 + rr) * 64 + cc4);
        }
        __syncthreads();
#pragma unroll 8
        for (int tt = 0; tt < 32; tt++) {
            float kr[4], vr[4];
            *(float4*)kr = *(const float4*)&ks[tt][i0];
            *(float4*)vr = *(const float4*)&vs[tt][j0];
#pragma unroll
            for (int a = 0; a < 4; a++)
#pragma unroll
                for (int b = 0; b < 4; b++)
                    s[a][b] = fmaf(kr[a], vr[b], s[a][b]);
            if (zowner) {
#pragma unroll
                for (int a = 0; a < 4; a++) z[a] += kr[a];
            }
        }
        __syncthreads();
    }

    float* Sp = g_Sc + ((size_t)bh * NCHUNK + c) * (Dq * Dq);
#pragma unroll
    for (int a = 0; a < 4; a++)
        *(float4*)&Sp[(i0 + a) * Dq + j0] = make_float4(s[a][0], s[a][1], s[a][2], s[a][3]);
    if (zowner) {
        float* zp = g_zc + ((size_t)bh * NCHUNK + c) * Dq;
#pragma unroll
        for (int a = 0; a < 4; a++) zp[i0 + a] = z[a];
    }
}

// ---------------- exclusive scan over chunks ---------------------------------
__global__ __launch_bounds__(256)
void scan_kernel()
{
    const int bh = blockIdx.x;
    const int tid = threadIdx.x;
    const size_t base = (size_t)bh * NCHUNK;

    float run[16];
#pragma unroll
    for (int l = 0; l < 16; l++) run[l] = 0.f;
    float zrun = 0.f;

    for (int c = 0; c < NCHUNK; c++) {
        float*       sp = g_Sp + (base + c) * (Dq * Dq) + tid * 16;
        const float* sc = g_Sc + (base + c) * (Dq * Dq) + tid * 16;
#pragma unroll
        for (int l = 0; l < 16; l++) {
            sp[l] = run[l];
            run[l] += sc[l];
        }
        if (tid < Dq) {
            g_zp[(base + c) * Dq + tid] = zrun;
            zrun += g_zc[(base + c) * Dq + tid];
        }
    }
}

// ---------------- per-chunk attention (half-chunk blocks) --------------------
#define AT_QS 0
#define AT_KS 4096
#define AT_A  12544
#define AT_S  20736
#define AT_Z  24832
#define AT_D  24896
#define AT_TOTAL 24960
#define AT_BYTES (AT_TOTAL * 4)   // 99840

__global__ __launch_bounds__(256)
void attn_kernel()
{
    extern __shared__ float sm[];
    float* Qs   = sm + AT_QS;
    float* Ks   = sm + AT_KS;
    float* Asm  = sm + AT_A;
    float* Ss   = sm + AT_S;
    float* zs   = sm + AT_Z;
    float* dens = sm + AT_D;

    const int c    = blockIdx.x >> 1;
    const int half = blockIdx.x & 1;
    const int bh   = blockIdx.y;
    const int tid  = threadIdx.x;
    const int r0   = half << 6;
    const int SEND = r0 + 64;
    const size_t coff = ((size_t)bh * Tq + c * LCHUNK) * Dq;
    const size_t qoff = coff + (size_t)r0 * Dq;
    const size_t soff = ((size_t)bh * NCHUNK + c) * (Dq * Dq);

    for (int f = tid; f < 1024; f += 256) {
        const int t = f >> 4, d4 = (f & 15) << 2;
        *(float4*)&Qs[t * 64 + d4] = *(const float4*)(g_q + qoff + (size_t)t * 64 + d4);
    }
    for (int f = tid; f < SEND * 16; f += 256) {
        const int d  = f & 63;
        const int t0 = (f >> 6) << 2;
        const float x0 = g_k[coff + (size_t)(t0 + 0) * 64 + d];
        const float x1 = g_k[coff + (size_t)(t0 + 1) * 64 + d];
        const float x2 = g_k[coff + (size_t)(t0 + 2) * 64 + d];
        const float x3 = g_k[coff + (size_t)(t0 + 3) * 64 + d];
        *(float4*)&Ks[d * 132 + t0] = make_float4(x0, x1, x2, x3);
    }
    for (int f = tid; f < 1024; f += 256)
        *(float4*)&Ss[f * 4] = *(const float4*)(g_Sp + soff + f * 4);
    if (tid < Dq) zs[tid] = g_zp[((size_t)bh * NCHUNK + c) * Dq + tid];
    __syncthreads();

    if (tid < 64) {
        float acc = EPSq;
#pragma unroll
        for (int d0 = 0; d0 < 64; d0 += 4) {
            float4 q4 = *(const float4*)&Qs[tid * 64 + d0];
            float4 z4 = *(const float4*)&zs[d0];
            acc += q4.x * z4.x + q4.y * z4.y + q4.z * z4.z + q4.w * z4.w;
        }
        dens[tid] = acc;
    }
    __syncthreads();

    const int trow = (tid >> 4) << 2;

    if (half) {
        const int tcol = (tid & 15) << 3;
        float a1[4][8];
#pragma unroll
        for (int i = 0; i < 4; i++)
#pragma unroll
            for (int j = 0; j < 8; j++) a1[i][j] = 0.f;
        for (int d0 = 0; d0 < 64; d0 += 4) {
            float kr[4][8];
#pragma unroll
            for (int l = 0; l < 4; l++) {
                *(float4*)(&kr[l][0]) = *(const float4*)&Ks[(d0 + l) * 132 + tcol];
                *(float4*)(&kr[l][4]) = *(const float4*)&Ks[(d0 + l) * 132 + tcol + 4];
            }
#pragma unroll
            for (int i = 0; i < 4; i++) {
                float4 q4 = *(const float4*)&Qs[(trow + i) * 64 + d0];
                const float qa[4] = {q4.x, q4.y, q4.z, q4.w};
#pragma unroll
                for (int l = 0; l < 4; l++)
#pragma unroll
                    for (int j = 0; j < 8; j++)
                        a1[i][j] = fmaf(qa[l], kr[l][j], a1[i][j]);
            }
        }
#pragma unroll
        for (int i = 0; i < 4; i++) {
            const int tl = trow + i;
            const int tg = r0 + tl;
            float rs = 0.f;
#pragma unroll
            for (int j = 0; j < 8; j++) {
                const int s = tcol + j;
                const float v = (s <= tg) ? a1[i][j] : 0.f;
                a1[i][j] = v;
                rs += v;
            }
            *(float4*)&Asm[tl * 128 + tcol]     = make_float4(a1[i][0], a1[i][1], a1[i][2], a1[i][3]);
            *(float4*)&Asm[tl * 128 + tcol + 4] = make_float4(a1[i][4], a1[i][5], a1[i][6], a1[i][7]);
            atomicAdd(&dens[tl], rs);
        }
    } else {
        const int tcol = (tid & 15) << 2;
        float a1[4][4];
#pragma unroll
        for (int i = 0; i < 4; i++)
#pragma unroll
            for (int j = 0; j < 4; j++) a1[i][j] = 0.f;
        for (int d0 = 0; d0 < 64; d0 += 4) {
            float kr[4][4];
#pragma unroll
            for (int l = 0; l < 4; l++)
                *(float4*)(&kr[l][0]) = *(const float4*)&Ks[(d0 + l) * 132 + tcol];
#pragma unroll
            for (int i = 0; i < 4; i++) {
                float4 q4 = *(const float4*)&Qs[(trow + i) * 64 + d0];
                const float qa[4] = {q4.x, q4.y, q4.z, q4.w};
#pragma unroll
                for (int l = 0; l < 4; l++)
#pragma unroll
                    for (int j = 0; j < 4; j++)
                        a1[i][j] = fmaf(qa[l], kr[l][j], a1[i][j]);
            }
        }
#pragma unroll
        for (int i = 0; i < 4; i++) {
            const int tl = trow + i;
            float rs = 0.f;
#pragma unroll
            for (int j = 0; j < 4; j++) {
                const int s = tcol + j;
                const float v = (s <= tl) ? a1[i][j] : 0.f;
                a1[i][j] = v;
                rs += v;
            }
            *(float4*)&Asm[tl * 128 + tcol] = make_float4(a1[i][0], a1[i][1], a1[i][2], a1[i][3]);
            atomicAdd(&dens[tl], rs);
        }
    }
    __syncthreads();

    for (int f = tid; f < SEND * 16; f += 256)
        *(float4*)&Ks[f * 4] = *(const float4*)(g_v + coff + f * 4);
    __syncthreads();

    const int jc = (tid & 15) << 2;
    float a2[4][4];
#pragma unroll
    for (int i = 0; i < 4; i++)
#pragma unroll
        for (int j = 0; j < 4; j++) a2[i][j] = 0.f;

    for (int s0 = 0; s0 < SEND; s0 += 4) {
        float vr[4][4];
#pragma unroll
        for (int l = 0; l < 4; l++)
            *(float4*)vr[l] = *(const float4*)&Ks[(s0 + l) * 64 + jc];
#pragma unroll
        for (int i = 0; i < 4; i++) {
            float4 av = *(const float4*)&Asm[(trow + i) * 128 + s0];
            const float aa[4] = {av.x, av.y, av.z, av.w};
#pragma unroll
            for (int l = 0; l < 4; l++)
#pragma unroll
                for (int j = 0; j < 4; j++)
                    a2[i][j] = fmaf(aa[l], vr[l][j], a2[i][j]);
        }
    }
    for (int d0 = 0; d0 < 64; d0 += 4) {
        float sr[4][4];
#pragma unroll
        for (int l = 0; l < 4; l++)
            *(float4*)sr[l] = *(const float4*)&Ss[(d0 + l) * 64 + jc];
#pragma unroll
        for (int i = 0; i < 4; i++) {
            float4 q4 = *(const float4*)&Qs[(trow + i) * 64 + d0];
            const float qa[4] = {q4.x, q4.y, q4.z, q4.w};
#pragma unroll
            for (int l = 0; l < 4; l++)
#pragma unroll
                for (int j = 0; j < 4; j++)
                    a2[i][j] = fmaf(qa[l], sr[l][j], a2[i][j]);
        }
    }

    const int b = bh >> 4, h = bh & 15;
#pragma unroll
    for (int i = 0; i < 4; i++) {
        const int tl = trow + i;
        const float inv = 1.0f / dens[tl];
        const size_t row = (size_t)b * Tq + c * LCHUNK + r0 + tl;
        const size_t idx = row * Cq + h * 64 + jc;
        float o0 = a2[i][0] * inv, o1 = a2[i][1] * inv;
        float o2 = a2[i][2] * inv, o3 = a2[i][3] * inv;
        __nv_bfloat16 h0 = __float2bfloat16(o0), h1 = __float2bfloat16(o1);
        __nv_bfloat16 h2 = __float2bfloat16(o2), h3 = __float2bfloat16(o3);
        __nv_bfloat16 l0 = __float2bfloat16(o0 - __bfloat162float(h0));
        __nv_bfloat16 l1 = __float2bfloat16(o1 - __bfloat162float(h1));
        __nv_bfloat16 l2 = __float2bfloat16(o2 - __bfloat162float(h2));
        __nv_bfloat16 l3 = __float2bfloat16(o3 - __bfloat162float(h3));
        uint2 uh, ul;
        uh.x = ((unsigned)__bfloat16_as_ushort(h1) << 16) | __bfloat16_as_ushort(h0);
        uh.y = ((unsigned)__bfloat16_as_ushort(h3) << 16) | __bfloat16_as_ushort(h2);
        ul.x = ((unsigned)__bfloat16_as_ushort(l1) << 16) | __bfloat16_as_ushort(l0);
        ul.y = ((unsigned)__bfloat16_as_ushort(l3) << 16) | __bfloat16_as_ushort(l2);
        *(uint2*)&g_yh[idx] = uh;
        *(uint2*)&g_yl[idx] = ul;
    }
}

// ---------------- launch -----------------------------------------------------
extern "C" void kernel_launch(void* const* d_in, const int* in_sizes, int n_in,
                              void* d_out, int out_size)
{
    const float* x      = (const float*)d_in[0];
    const float* w_attn = (const float*)d_in[1];
    const float* w_proj = (const float*)d_in[2];
    float* out = (float*)d_out;

    cudaFuncSetAttribute(attn_kernel, cudaFuncAttributeMaxDynamicSharedMemorySize, AT_BYTES);
    cudaFuncSetAttribute(mma_gemm<1>, cudaFuncAttributeMaxDynamicSharedMemorySize, GEMM_SMEM);
    cudaFuncSetAttribute(mma_gemm<2>, cudaFuncAttributeMaxDynamicSharedMemorySize, GEMM_SMEM);

    __nv_bfloat16 *xh, *xl, *wah, *wal, *wph, *wpl, *yh, *yl;
    cudaGetSymbolAddress((void**)&xh,  g_xh);
    cudaGetSymbolAddress((void**)&xl,  g_xl);
    cudaGetSymbolAddress((void**)&wah, g_wah);
    cudaGetSymbolAddress((void**)&wal, g_wal);
    cudaGetSymbolAddress((void**)&wph, g_wph);
    cudaGetSymbolAddress((void**)&wpl, g_wpl);
    cudaGetSymbolAddress((void**)&yh,  g_yh);
    cudaGetSymbolAddress((void**)&yl,  g_yl);

    split_kernel<<<(Mrows * Cq / 4 + 255) / 256, 256>>>(x, xh, xl, Mrows * Cq / 4);
    split_kernel<<<(Cq * 3 * Cq / 4 + 255) / 256, 256>>>(w_attn, wah, wal, Cq * 3 * Cq / 4);
    split_kernel<<<(Cq * Cq / 4 + 255) / 256, 256>>>(w_proj, wph, wpl, Cq * Cq / 4);

    mma_gemm<1><<<dim3(3 * Cq / 128, Mrows / 128), 256, GEMM_SMEM>>>(
        xh, xl, wah, wal, nullptr, 3 * Cq);
    chunk_sums_kernel<<<dim3(NCHUNK, BHq), 256>>>();
    scan_kernel<<<BHq, 256>>>();
    attn_kernel<<<dim3(2 * NCHUNK, BHq), 256, AT_BYTES>>>();
    mma_gemm<2><<<dim3(Cq / 128, Mrows / 128), 256, GEMM_SMEM>>>(
        yh, yl, wph, wpl, out, Cq);
}

// round 9
// speedup vs baseline: 1.9087x; 1.2549x over previous
#include <cuda_runtime.h>
#include <cuda_fp16.h>
#include <cuda_bf16.h>
#include <math.h>

// Problem constants
#define Bq 2
#define Tq 2048
#define Cq 1024
#define Hq 16
#define Dq 64
#define NCHUNK 16
#define LCHUNK 128
#define BHq (Bq * Hq)       // 32
#define Mrows (Bq * Tq)     // 4096
#define EPSq 1e-6f

// ---------------- scratch (device globals: no allocs allowed) ----------------
__device__ float g_q[(size_t)BHq * Tq * Dq];
__device__ float g_k[(size_t)BHq * Tq * Dq];
__device__ float g_v[(size_t)BHq * Tq * Dq];
__device__ float g_Sc[(size_t)BHq * NCHUNK * Dq * Dq];
__device__ float g_Sp[(size_t)BHq * NCHUNK * Dq * Dq];
__device__ float g_zc[(size_t)BHq * NCHUNK * Dq];
__device__ float g_zp[(size_t)BHq * NCHUNK * Dq];

// fp16 buffers: A-side split hi/lo, B-side (weights) single fp16.
__device__ __align__(16) __half g_xh[(size_t)Mrows * Cq];
__device__ __align__(16) __half g_xl[(size_t)Mrows * Cq];
__device__ __align__(16) __half g_wa[(size_t)Cq * 3 * Cq];
__device__ __align__(16) __half g_wp[(size_t)Cq * Cq];
__device__ __align__(16) __half g_yh[(size_t)Mrows * Cq];
__device__ __align__(16) __half g_yl[(size_t)Mrows * Cq];

// ---------------- fp32 -> fp16 hi/lo split ------------------------------------
__global__ __launch_bounds__(256)
void split2_kernel(const float* __restrict__ in, __half* __restrict__ hi,
                   __half* __restrict__ lo, int n4)
{
    const int i = blockIdx.x * 256 + threadIdx.x;
    if (i >= n4) return;
    float4 v = ((const float4*)in)[i];
    __half h0 = __float2half(v.x), h1 = __float2half(v.y);
    __half h2 = __float2half(v.z), h3 = __float2half(v.w);
    __half l0 = __float2half(v.x - __half2float(h0));
    __half l1 = __float2half(v.y - __half2float(h1));
    __half l2 = __float2half(v.z - __half2float(h2));
    __half l3 = __float2half(v.w - __half2float(h3));
    uint2 uh, ul;
    uh.x = ((unsigned)__half_as_ushort(h1) << 16) | __half_as_ushort(h0);
    uh.y = ((unsigned)__half_as_ushort(h3) << 16) | __half_as_ushort(h2);
    ul.x = ((unsigned)__half_as_ushort(l1) << 16) | __half_as_ushort(l0);
    ul.y = ((unsigned)__half_as_ushort(l3) << 16) | __half_as_ushort(l2);
    ((uint2*)hi)[i] = uh;
    ((uint2*)lo)[i] = ul;
}

// ---------------- fp32 -> fp16 (hi only, for weights) -------------------------
__global__ __launch_bounds__(256)
void split1_kernel(const float* __restrict__ in, __half* __restrict__ hi, int n4)
{
    const int i = blockIdx.x * 256 + threadIdx.x;
    if (i >= n4) return;
    float4 v = ((const float4*)in)[i];
    __half h0 = __float2half(v.x), h1 = __float2half(v.y);
    __half h2 = __float2half(v.z), h3 = __float2half(v.w);
    uint2 uh;
    uh.x = ((unsigned)__half_as_ushort(h1) << 16) | __half_as_ushort(h0);
    uh.y = ((unsigned)__half_as_ushort(h3) << 16) | __half_as_ushort(h2);
    ((uint2*)hi)[i] = uh;
}

// ---------------- MMA helpers ------------------------------------------------
__device__ __forceinline__ void ldsm_x4(uint4& r, unsigned addr) {
    asm volatile("ldmatrix.sync.aligned.m8n8.x4.shared.b16 {%0,%1,%2,%3}, [%4];"
                 : "=r"(r.x), "=r"(r.y), "=r"(r.z), "=r"(r.w) : "r"(addr));
}
__device__ __forceinline__ void ldsm_x4t(uint4& r, unsigned addr) {
    asm volatile("ldmatrix.sync.aligned.m8n8.x4.trans.shared.b16 {%0,%1,%2,%3}, [%4];"
                 : "=r"(r.x), "=r"(r.y), "=r"(r.z), "=r"(r.w) : "r"(addr));
}
__device__ __forceinline__ void mma_fp16(float c[4], const uint4& a, unsigned b0, unsigned b1) {
    asm volatile("mma.sync.aligned.m16n8k16.row.col.f32.f16.f16.f32 "
                 "{%0,%1,%2,%3},{%4,%5,%6,%7},{%8,%9},{%0,%1,%2,%3};"
                 : "+f"(c[0]), "+f"(c[1]), "+f"(c[2]), "+f"(c[3])
                 : "r"(a.x), "r"(a.y), "r"(a.z), "r"(a.w), "r"(b0), "r"(b1));
}
__device__ __forceinline__ void cp16(unsigned s, const void* g) {
    asm volatile("cp.async.cg.shared.global [%0], [%1], 16;\n" :: "r"(s), "l"(g));
}

// ---------------- fp16-split tensor-core GEMM, K-step 64 ---------------------
// C = (Ah+Al) @ B, fp32 accumulate. 2 MMAs per fragment pair.
// Per stage: Ah 16K | Al 16K | B 16K = 48KB; 2 stages.
#define STAGE_BYTES 49152
#define GEMM_SMEM   (2 * STAGE_BYTES)

template <int MODE>
__global__ __launch_bounds__(256)
void mma_gemm(const __half* __restrict__ Ah, const __half* __restrict__ Al,
              const __half* __restrict__ Bm,
              float* __restrict__ Cout, int N)
{
    constexpr int K = 1024;
    constexpr int KSTEP = 64;
    constexpr int NITER = K / KSTEP;     // 16
    extern __shared__ char smem[];
    const unsigned sbase = (unsigned)__cvta_generic_to_shared(smem);

    const int tid = threadIdx.x;
    const int lane = tid & 31, wid = tid >> 5;
    const int warp_m = wid >> 2, warp_n = wid & 3;
    const int bm = blockIdx.y * 128, bn = blockIdx.x * 128;

    // A tile: 128 rows x 64 fp16 (8 granules/row), swizzle c ^ (row&7)
    // B tile:  64 rows x 128 fp16 (16 granules/row), swizzle (g&8)|((g&7)^(row&7))
    int sA[4], sB[4], gAr[4], gAc[4], gBr[4], gBc[4];
#pragma unroll
    for (int j = 0; j < 4; j++) {
        const int f = tid + j * 256;          // 0..1023
        const int ar = f >> 3, ac = f & 7;
        sA[j] = (ar * 8 + (ac ^ (ar & 7))) * 16;
        gAr[j] = ar; gAc[j] = ac * 8;
        const int br = f >> 4, bg = f & 15;
        sB[j] = (br * 16 + ((bg & 8) | ((bg & 7) ^ (br & 7)))) * 16;
        gBr[j] = br; gBc[j] = bg * 8;
    }

    const int arow_l = warp_m * 64 + (lane & 15);
    const int aghalf = (lane >> 4) & 1;
    int aOff[4][4];
#pragma unroll
    for (int mi = 0; mi < 4; mi++) {
        const int row = arow_l + mi * 16;
        const int rsw = row & 7;
#pragma unroll
        for (int kx = 0; kx < 4; kx++) {
            const int c = kx * 2 + aghalf;
            aOff[mi][kx] = (row * 8 + (c ^ rsw)) * 16;
        }
    }
    const int bk_l = (lane & 7) + ((lane >> 3) & 1) * 8;
    const int gadd = lane >> 4;
    const int klow = bk_l & 7;
    int bOff[4][2];
#pragma unroll
    for (int kx = 0; kx < 4; kx++) {
        const int k = kx * 16 + bk_l;
#pragma unroll
        for (int np = 0; np < 2; np++) {
            const int g = warp_n * 4 + np * 2 + gadd;
            bOff[kx][np] = (k * 16 + ((g & 8) | ((g & 7) ^ klow))) * 16;
        }
    }

    float acc[4][4][4];
#pragma unroll
    for (int mi = 0; mi < 4; mi++)
#pragma unroll
        for (int ni = 0; ni < 4; ni++)
#pragma unroll
            for (int r = 0; r < 4; r++) acc[mi][ni][r] = 0.f;

    auto issue = [&](int stage, int k0) {
        const unsigned st = sbase + stage * STAGE_BYTES;
#pragma unroll
        for (int j = 0; j < 4; j++) {
            const size_t aoff = (size_t)(bm + gAr[j]) * K + k0 + gAc[j];
            const size_t boff = (size_t)(k0 + gBr[j]) * N + bn + gBc[j];
            cp16(st + sA[j],         Ah + aoff);
            cp16(st + 16384 + sA[j], Al + aoff);
            cp16(st + 32768 + sB[j], Bm + boff);
        }
        asm volatile("cp.async.commit_group;");
    };

    issue(0, 0);
    issue(1, KSTEP);

    for (int it = 0; it < NITER; it++) {
        asm volatile("cp.async.wait_group 1;");
        __syncthreads();
        const unsigned st = sbase + (it & 1) * STAGE_BYTES;
#pragma unroll
        for (int kx = 0; kx < 4; kx++) {
            uint4 Afh[4], Afl[4], Bf[2];
#pragma unroll
            for (int mi = 0; mi < 4; mi++) {
                ldsm_x4(Afh[mi], st + aOff[mi][kx]);
                ldsm_x4(Afl[mi], st + 16384 + aOff[mi][kx]);
            }
#pragma unroll
            for (int np = 0; np < 2; np++)
                ldsm_x4t(Bf[np], st + 32768 + bOff[kx][np]);
#pragma unroll
            for (int mi = 0; mi < 4; mi++)
#pragma unroll
                for (int ni = 0; ni < 4; ni++) {
                    const int np = ni >> 1;
                    const unsigned b0 = (ni & 1) ? Bf[np].z : Bf[np].x;
                    const unsigned b1 = (ni & 1) ? Bf[np].w : Bf[np].y;
                    mma_fp16(acc[mi][ni], Afh[mi], b0, b1);
                    mma_fp16(acc[mi][ni], Afl[mi], b0, b1);
                }
        }
        __syncthreads();
        if (it + 2 < NITER) issue(it & 1, (it + 2) * KSTEP);
        else asm volatile("cp.async.commit_group;");
    }

    const int rbase = bm + warp_m * 64 + (lane >> 2);
    const int cbase = bn + warp_n * 32 + (lane & 3) * 2;
#pragma unroll
    for (int ni = 0; ni < 4; ni++) {
        const int c = cbase + ni * 8;
        if (MODE == 2) {
#pragma unroll
            for (int mi = 0; mi < 4; mi++) {
#pragma unroll
                for (int half = 0; half < 2; half++) {
                    const int r = rbase + mi * 16 + half * 8;
                    *(float2*)&Cout[(size_t)r * N + c] =
                        make_float2(acc[mi][ni][half * 2], acc[mi][ni][half * 2 + 1]);
                }
            }
        } else {
            const int seg = c >> 10;
            const int cc = c & 1023;
            const int h = cc >> 6, d0 = cc & 63;
            float* dstb = (seg == 0) ? g_q : (seg == 1) ? g_k : g_v;
#pragma unroll
            for (int mi = 0; mi < 4; mi++) {
#pragma unroll
                for (int half = 0; half < 2; half++) {
                    const int r = rbase + mi * 16 + half * 8;
                    const int b = r >> 11, t = r & 2047;
                    float v0 = acc[mi][ni][half * 2], v1 = acc[mi][ni][half * 2 + 1];
                    if (seg < 2) {
                        v0 = (v0 > 0.f) ? (v0 + 1.f) : expf(v0);
                        v1 = (v1 > 0.f) ? (v1 + 1.f) : expf(v1);
                    }
                    const size_t idx = ((size_t)(b * Hq + h) * Tq + t) * Dq + d0;
                    *(float2*)&dstb[idx] = make_float2(v0, v1);
                }
            }
        }
    }
}

// ---------------- per-chunk K^T V sums + k sums ------------------------------
__global__ __launch_bounds__(256)
void chunk_sums_kernel()
{
    const int c  = blockIdx.x;
    const int bh = blockIdx.y;
    const int tid = threadIdx.x;
    const int i0 = (tid >> 4) << 2;
    const int j0 = (tid & 15) << 2;
    const bool zowner = ((tid & 15) == 0);

    const float* kb = g_k + ((size_t)bh * Tq + c * LCHUNK) * Dq;
    const float* vb = g_v + ((size_t)bh * Tq + c * LCHUNK) * Dq;

    __shared__ float ks[32][64];
    __shared__ float vs[32][64];

    float s[4][4];
#pragma unroll
    for (int a = 0; a < 4; a++)
#pragma unroll
        for (int b = 0; b < 4; b++) s[a][b] = 0.f;
    float z[4] = {0.f, 0.f, 0.f, 0.f};

    for (int t0 = 0; t0 < LCHUNK; t0 += 32) {
#pragma unroll
        for (int l = 0; l < 2; l++) {
            const int f = tid * 2 + l;
            const int rr = f >> 4, cc4 = (f & 15) << 2;
            *(float4*)&ks[rr][cc4] = *(const float4*)(kb + (size_t)(t0 + rr) * 64 + cc4);
            *(float4*)&vs[rr][cc4] = *(const float4*)(vb + (size_t)(t0 + rr) * 64 + cc4);
        }
        __syncthreads();
#pragma unroll 8
        for (int tt = 0; tt < 32; tt++) {
            float kr[4], vr[4];
            *(float4*)kr = *(const float4*)&ks[tt][i0];
            *(float4*)vr = *(const float4*)&vs[tt][j0];
#pragma unroll
            for (int a = 0; a < 4; a++)
#pragma unroll
                for (int b = 0; b < 4; b++)
                    s[a][b] = fmaf(kr[a], vr[b], s[a][b]);
            if (zowner) {
#pragma unroll
                for (int a = 0; a < 4; a++) z[a] += kr[a];
            }
        }
        __syncthreads();
    }

    float* Sp = g_Sc + ((size_t)bh * NCHUNK + c) * (Dq * Dq);
#pragma unroll
    for (int a = 0; a < 4; a++)
        *(float4*)&Sp[(i0 + a) * Dq + j0] = make_float4(s[a][0], s[a][1], s[a][2], s[a][3]);
    if (zowner) {
        float* zp = g_zc + ((size_t)bh * NCHUNK + c) * Dq;
#pragma unroll
        for (int a = 0; a < 4; a++) zp[i0 + a] = z[a];
    }
}

// ---------------- exclusive scan over chunks ---------------------------------
__global__ __launch_bounds__(256)
void scan_kernel()
{
    const int bh = blockIdx.x;
    const int tid = threadIdx.x;
    const size_t base = (size_t)bh * NCHUNK;

    float run[16];
#pragma unroll
    for (int l = 0; l < 16; l++) run[l] = 0.f;
    float zrun = 0.f;

    for (int c = 0; c < NCHUNK; c++) {
        float*       sp = g_Sp + (base + c) * (Dq * Dq) + tid * 16;
        const float* sc = g_Sc + (base + c) * (Dq * Dq) + tid * 16;
#pragma unroll
        for (int l = 0; l < 16; l++) {
            sp[l] = run[l];
            run[l] += sc[l];
        }
        if (tid < Dq) {
            g_zp[(base + c) * Dq + tid] = zrun;
            zrun += g_zc[(base + c) * Dq + tid];
        }
    }
}

// ---------------- per-chunk attention (half-chunk blocks) --------------------
#define AT_QS 0
#define AT_KS 4096
#define AT_A  12544
#define AT_S  20736
#define AT_Z  24832
#define AT_D  24896
#define AT_TOTAL 24960
#define AT_BYTES (AT_TOTAL * 4)   // 99840

__global__ __launch_bounds__(256)
void attn_kernel()
{
    extern __shared__ float sm[];
    float* Qs   = sm + AT_QS;
    float* Ks   = sm + AT_KS;
    float* Asm  = sm + AT_A;
    float* Ss   = sm + AT_S;
    float* zs   = sm + AT_Z;
    float* dens = sm + AT_D;

    const int c    = blockIdx.x >> 1;
    const int half = blockIdx.x & 1;
    const int bh   = blockIdx.y;
    const int tid  = threadIdx.x;
    const int r0   = half << 6;
    const int SEND = r0 + 64;
    const size_t coff = ((size_t)bh * Tq + c * LCHUNK) * Dq;
    const size_t qoff = coff + (size_t)r0 * Dq;
    const size_t soff = ((size_t)bh * NCHUNK + c) * (Dq * Dq);

    for (int f = tid; f < 1024; f += 256) {
        const int t = f >> 4, d4 = (f & 15) << 2;
        *(float4*)&Qs[t * 64 + d4] = *(const float4*)(g_q + qoff + (size_t)t * 64 + d4);
    }
    for (int f = tid; f < SEND * 16; f += 256) {
        const int d  = f & 63;
        const int t0 = (f >> 6) << 2;
        const float x0 = g_k[coff + (size_t)(t0 + 0) * 64 + d];
        const float x1 = g_k[coff + (size_t)(t0 + 1) * 64 + d];
        const float x2 = g_k[coff + (size_t)(t0 + 2) * 64 + d];
        const float x3 = g_k[coff + (size_t)(t0 + 3) * 64 + d];
        *(float4*)&Ks[d * 132 + t0] = make_float4(x0, x1, x2, x3);
    }
    for (int f = tid; f < 1024; f += 256)
        *(float4*)&Ss[f * 4] = *(const float4*)(g_Sp + soff + f * 4);
    if (tid < Dq) zs[tid] = g_zp[((size_t)bh * NCHUNK + c) * Dq + tid];
    __syncthreads();

    if (tid < 64) {
        float acc = EPSq;
#pragma unroll
        for (int d0 = 0; d0 < 64; d0 += 4) {
            float4 q4 = *(const float4*)&Qs[tid * 64 + d0];
            float4 z4 = *(const float4*)&zs[d0];
            acc += q4.x * z4.x + q4.y * z4.y + q4.z * z4.z + q4.w * z4.w;
        }
        dens[tid] = acc;
    }
    __syncthreads();

    const int trow = (tid >> 4) << 2;

    if (half) {
        const int tcol = (tid & 15) << 3;
        float a1[4][8];
#pragma unroll
        for (int i = 0; i < 4; i++)
#pragma unroll
            for (int j = 0; j < 8; j++) a1[i][j] = 0.f;
        for (int d0 = 0; d0 < 64; d0 += 4) {
            float kr[4][8];
#pragma unroll
            for (int l = 0; l < 4; l++) {
                *(float4*)(&kr[l][0]) = *(const float4*)&Ks[(d0 + l) * 132 + tcol];
                *(float4*)(&kr[l][4]) = *(const float4*)&Ks[(d0 + l) * 132 + tcol + 4];
            }
#pragma unroll
            for (int i = 0; i < 4; i++) {
                float4 q4 = *(const float4*)&Qs[(trow + i) * 64 + d0];
                const float qa[4] = {q4.x, q4.y, q4.z, q4.w};
#pragma unroll
                for (int l = 0; l < 4; l++)
#pragma unroll
                    for (int j = 0; j < 8; j++)
                        a1[i][j] = fmaf(qa[l], kr[l][j], a1[i][j]);
            }
        }
#pragma unroll
        for (int i = 0; i < 4; i++) {
            const int tl = trow + i;
            const int tg = r0 + tl;
            float rs = 0.f;
#pragma unroll
            for (int j = 0; j < 8; j++) {
                const int s = tcol + j;
                const float v = (s <= tg) ? a1[i][j] : 0.f;
                a1[i][j] = v;
                rs += v;
            }
            *(float4*)&Asm[tl * 128 + tcol]     = make_float4(a1[i][0], a1[i][1], a1[i][2], a1[i][3]);
            *(float4*)&Asm[tl * 128 + tcol + 4] = make_float4(a1[i][4], a1[i][5], a1[i][6], a1[i][7]);
            atomicAdd(&dens[tl], rs);
        }
    } else {
        const int tcol = (tid & 15) << 2;
        float a1[4][4];
#pragma unroll
        for (int i = 0; i < 4; i++)
#pragma unroll
            for (int j = 0; j < 4; j++) a1[i][j] = 0.f;
        for (int d0 = 0; d0 < 64; d0 += 4) {
            float kr[4][4];
#pragma unroll
            for (int l = 0; l < 4; l++)
                *(float4*)(&kr[l][0]) = *(const float4*)&Ks[(d0 + l) * 132 + tcol];
#pragma unroll
            for (int i = 0; i < 4; i++) {
                float4 q4 = *(const float4*)&Qs[(trow + i) * 64 + d0];
                const float qa[4] = {q4.x, q4.y, q4.z, q4.w};
#pragma unroll
                for (int l = 0; l < 4; l++)
#pragma unroll
                    for (int j = 0; j < 4; j++)
                        a1[i][j] = fmaf(qa[l], kr[l][j], a1[i][j]);
            }
        }
#pragma unroll
        for (int i = 0; i < 4; i++) {
            const int tl = trow + i;
            float rs = 0.f;
#pragma unroll
            for (int j = 0; j < 4; j++) {
                const int s = tcol + j;
                const float v = (s <= tl) ? a1[i][j] : 0.f;
                a1[i][j] = v;
                rs += v;
            }
            *(float4*)&Asm[tl * 128 + tcol] = make_float4(a1[i][0], a1[i][1], a1[i][2], a1[i][3]);
            atomicAdd(&dens[tl], rs);
        }
    }
    __syncthreads();

    for (int f = tid; f < SEND * 16; f += 256)
        *(float4*)&Ks[f * 4] = *(const float4*)(g_v + coff + f * 4);
    __syncthreads();

    const int jc = (tid & 15) << 2;
    float a2[4][4];
#pragma unroll
    for (int i = 0; i < 4; i++)
#pragma unroll
        for (int j = 0; j < 4; j++) a2[i][j] = 0.f;

    for (int s0 = 0; s0 < SEND; s0 += 4) {
        float vr[4][4];
#pragma unroll
        for (int l = 0; l < 4; l++)
            *(float4*)vr[l] = *(const float4*)&Ks[(s0 + l) * 64 + jc];
#pragma unroll
        for (int i = 0; i < 4; i++) {
            float4 av = *(const float4*)&Asm[(trow + i) * 128 + s0];
            const float aa[4] = {av.x, av.y, av.z, av.w};
#pragma unroll
            for (int l = 0; l < 4; l++)
#pragma unroll
                for (int j = 0; j < 4; j++)
                    a2[i][j] = fmaf(aa[l], vr[l][j], a2[i][j]);
        }
    }
    for (int d0 = 0; d0 < 64; d0 += 4) {
        float sr[4][4];
#pragma unroll
        for (int l = 0; l < 4; l++)
            *(float4*)sr[l] = *(const float4*)&Ss[(d0 + l) * 64 + jc];
#pragma unroll
        for (int i = 0; i < 4; i++) {
            float4 q4 = *(const float4*)&Qs[(trow + i) * 64 + d0];
            const float qa[4] = {q4.x, q4.y, q4.z, q4.w};
#pragma unroll
            for (int l = 0; l < 4; l++)
#pragma unroll
                for (int j = 0; j < 4; j++)
                    a2[i][j] = fmaf(qa[l], sr[l][j], a2[i][j]);
        }
    }

    const int b = bh >> 4, h = bh & 15;
#pragma unroll
    for (int i = 0; i < 4; i++) {
        const int tl = trow + i;
        const float inv = 1.0f / dens[tl];
        const size_t row = (size_t)b * Tq + c * LCHUNK + r0 + tl;
        const size_t idx = row * Cq + h * 64 + jc;
        float o0 = a2[i][0] * inv, o1 = a2[i][1] * inv;
        float o2 = a2[i][2] * inv, o3 = a2[i][3] * inv;
        __half h0 = __float2half(o0), h1 = __float2half(o1);
        __half h2 = __float2half(o2), h3 = __float2half(o3);
        __half l0 = __float2half(o0 - __half2float(h0));
        __half l1 = __float2half(o1 - __half2float(h1));
        __half l2 = __float2half(o2 - __half2float(h2));
        __half l3 = __float2half(o3 - __half2float(h3));
        uint2 uh, ul;
        uh.x = ((unsigned)__half_as_ushort(h1) << 16) | __half_as_ushort(h0);
        uh.y = ((unsigned)__half_as_ushort(h3) << 16) | __half_as_ushort(h2);
        ul.x = ((unsigned)__half_as_ushort(l1) << 16) | __half_as_ushort(l0);
        ul.y = ((unsigned)__half_as_ushort(l3) << 16) | __half_as_ushort(l2);
        *(uint2*)&g_yh[idx] = uh;
        *(uint2*)&g_yl[idx] = ul;
    }
}

// ---------------- launch -----------------------------------------------------
extern "C" void kernel_launch(void* const* d_in, const int* in_sizes, int n_in,
                              void* d_out, int out_size)
{
    const float* x      = (const float*)d_in[0];
    const float* w_attn = (const float*)d_in[1];
    const float* w_proj = (const float*)d_in[2];
    float* out = (float*)d_out;

    cudaFuncSetAttribute(attn_kernel, cudaFuncAttributeMaxDynamicSharedMemorySize, AT_BYTES);
    cudaFuncSetAttribute(mma_gemm<1>, cudaFuncAttributeMaxDynamicSharedMemorySize, GEMM_SMEM);
    cudaFuncSetAttribute(mma_gemm<2>, cudaFuncAttributeMaxDynamicSharedMemorySize, GEMM_SMEM);

    __half *xh, *xl, *wa, *wp, *yh, *yl;
    cudaGetSymbolAddress((void**)&xh, g_xh);
    cudaGetSymbolAddress((void**)&xl, g_xl);
    cudaGetSymbolAddress((void**)&wa, g_wa);
    cudaGetSymbolAddress((void**)&wp, g_wp);
    cudaGetSymbolAddress((void**)&yh, g_yh);
    cudaGetSymbolAddress((void**)&yl, g_yl);

    split2_kernel<<<(Mrows * Cq / 4 + 255) / 256, 256>>>(x, xh, xl, Mrows * Cq / 4);
    split1_kernel<<<(Cq * 3 * Cq / 4 + 255) / 256, 256>>>(w_attn, wa, Cq * 3 * Cq / 4);
    split1_kernel<<<(Cq * Cq / 4 + 255) / 256, 256>>>(w_proj, wp, Cq * Cq / 4);

    mma_gemm<1><<<dim3(3 * Cq / 128, Mrows / 128), 256, GEMM_SMEM>>>(
        xh, xl, wa, nullptr, 3 * Cq);
    chunk_sums_kernel<<<dim3(NCHUNK, BHq), 256>>>();
    scan_kernel<<<BHq, 256>>>();
    attn_kernel<<<dim3(2 * NCHUNK, BHq), 256, AT_BYTES>>>();
    mma_gemm<2><<<dim3(Cq / 128, Mrows / 128), 256, GEMM_SMEM>>>(
        yh, yl, wp, out, Cq);
}